// round 1
// baseline (speedup 1.0000x reference)
#include <cuda_runtime.h>
#include <math.h>

#define BB   8
#define FIN  64
#define NPTS 2048
#define KNN  20
#define CI1  128
#define CO1  256
#define R1   11
#define J1   10
#define CO2  256
#define T2   40
#define KDIM2 (CI1*T2)          // 5120
#define NPOS  (BB*NPTS)          // 16384
#define EE_PER_POS (CI1*KNN)     // 2560
#define H_PER_POS  (CO1*J1)      // 2560
#define BN_EPS 1e-5f

// ---------------- scratch (device globals; no allocations allowed) ----------
__device__ float g_xt[NPOS*FIN];                 // [pos][d]
__device__ float g_sq[NPOS];
__device__ float g_dist[(size_t)NPOS*NPTS];      // [pos][j]   134 MB
__device__ int   g_idx[NPOS*KNN];
__device__ float g_w1t[CI1*R1*CO1];              // [(ci*11+r)][co]
__device__ float g_w2t[KDIM2*CO2];               // [(ci*40+t)][co]
__device__ float g_ee[(size_t)NPOS*EE_PER_POS];  // [pos][t][ci] 168 MB
__device__ float g_h[(size_t)NPOS*H_PER_POS];    // [pos][co][j] 168 MB
__device__ float g_out2[(size_t)NPOS*CO2];       // [pos][co]    16.8 MB
__device__ float g_s1[CO1], g_ss1[CO1], g_s2[CO2], g_ss2[CO2];
__device__ float g_a1[CO1], g_c1[CO1], g_a2[CO2], g_c2[CO2];

// ---------------- tiny prep kernels ----------------------------------------
__global__ void k_zero() {
    int t = threadIdx.x;
    g_s1[t] = 0.f; g_ss1[t] = 0.f; g_s2[t] = 0.f; g_ss2[t] = 0.f;
}

__global__ void k_xt(const float* __restrict__ x) {
    int pos = blockIdx.x;
    int b = pos >> 11, n = pos & (NPTS-1);
    int d = threadIdx.x;
    float v = x[((size_t)(b*FIN + d))*NPTS + n];
    g_xt[pos*FIN + d] = v;
    __shared__ float red[FIN];
    red[d] = v*v;
    __syncthreads();
    #pragma unroll
    for (int s = 32; s > 0; s >>= 1) {
        if (d < s) red[d] += red[d+s];
        __syncthreads();
    }
    if (d == 0) g_sq[pos] = red[0];
}

__global__ void k_w1t(const float* __restrict__ w1) {
    int e = blockIdx.x*256 + threadIdx.x;
    if (e >= CO1*CI1*R1) return;
    int co = e / (CI1*R1);
    int rem = e - co*(CI1*R1);
    int ci = rem / R1, r = rem - ci*R1;
    g_w1t[(ci*R1 + r)*CO1 + co] = w1[e];
}

__global__ void k_w2t(const float* __restrict__ w2) {
    int e = blockIdx.x*256 + threadIdx.x;
    if (e >= CO2*CI1*T2) return;
    int co = e / (CI1*T2);
    int rem = e - co*(CI1*T2);
    int ci = rem / T2, t = rem - ci*T2;
    g_w2t[(ci*T2 + t)*CO2 + co] = w2[e];
}

// ---------------- pairwise squared distances --------------------------------
__global__ __launch_bounds__(256) void k_dist() {
    __shared__ float si[32][65], sj[32][65];
    int b  = blockIdx.z;
    int i0 = blockIdx.y*32, j0 = blockIdx.x*32;
    int t  = threadIdx.y*16 + threadIdx.x;
    for (int e = t; e < 2048; e += 256) {
        int r = e >> 6, d = e & 63;
        si[r][d] = g_xt[((size_t)(b*NPTS) + i0 + r)*FIN + d];
        sj[r][d] = g_xt[((size_t)(b*NPTS) + j0 + r)*FIN + d];
    }
    __syncthreads();
    int iy = threadIdx.y, jx = threadIdx.x;
    float d00=0.f, d01=0.f, d10=0.f, d11=0.f;
    #pragma unroll
    for (int d = 0; d < 64; d++) {
        float a0 = si[iy][d],    a1 = si[iy+16][d];
        float c0 = sj[jx][d],    c1 = sj[jx+16][d];
        d00 += a0*c0; d01 += a0*c1; d10 += a1*c0; d11 += a1*c1;
    }
    float sqi0 = g_sq[b*NPTS + i0 + iy],   sqi1 = g_sq[b*NPTS + i0 + iy + 16];
    float sqj0 = g_sq[b*NPTS + j0 + jx],   sqj1 = g_sq[b*NPTS + j0 + jx + 16];
    size_t base0 = ((size_t)(b*NPTS) + i0 + iy)*NPTS + j0;
    size_t base1 = ((size_t)(b*NPTS) + i0 + iy + 16)*NPTS + j0;
    g_dist[base0 + jx]      = sqi0 + sqj0 - 2.f*d00;
    g_dist[base0 + jx + 16] = sqi0 + sqj1 - 2.f*d01;
    g_dist[base1 + jx]      = sqi1 + sqj0 - 2.f*d10;
    g_dist[base1 + jx + 16] = sqi1 + sqj1 - 2.f*d11;
}

// ---------------- top-20 (ascending distance, index tie-break) ---------------
__global__ __launch_bounds__(256) void k_knn() {
    __shared__ float sd[NPTS];
    __shared__ float rv[256];
    __shared__ int   ri[256];
    int pos = blockIdx.x;
    int i = pos & (NPTS-1);
    int tid = threadIdx.x;
    const float* row = g_dist + (size_t)pos*NPTS;
    for (int j = tid; j < NPTS; j += 256) sd[j] = row[j];
    __syncthreads();
    if (tid == 0) sd[i] = 1e30f;   // exclude self (reference drops idx[...,0] = self)
    __syncthreads();
    for (int kk = 0; kk < KNN; kk++) {
        float bv = 1e30f; int bi = 0x7fffffff;
        for (int j = tid; j < NPTS; j += 256) {
            float v = sd[j];
            if (v < bv) { bv = v; bi = j; }   // strided ascending j => first hit = smallest idx
        }
        rv[tid] = bv; ri[tid] = bi;
        __syncthreads();
        #pragma unroll
        for (int s = 128; s > 0; s >>= 1) {
            if (tid < s) {
                float v2 = rv[tid+s]; int i2 = ri[tid+s];
                if (v2 < rv[tid] || (v2 == rv[tid] && i2 < ri[tid])) { rv[tid] = v2; ri[tid] = i2; }
            }
            __syncthreads();
        }
        if (tid == 0) { g_idx[pos*KNN + kk] = ri[0]; sd[ri[0]] = 1e30f; }
        __syncthreads();
    }
}

// ---------------- edge features ee[pos][t][ci] -------------------------------
__global__ __launch_bounds__(256) void k_ee() {
    int pos = blockIdx.x;
    int b = pos >> 11;
    __shared__ float ctr[FIN];
    __shared__ int   nb[KNN];
    if (threadIdx.x < FIN) ctr[threadIdx.x] = g_xt[pos*FIN + threadIdx.x];
    if (threadIdx.x < KNN) nb[threadIdx.x]  = g_idx[pos*KNN + threadIdx.x];
    __syncthreads();
    for (int e = threadIdx.x; e < EE_PER_POS; e += 256) {
        int t = e >> 7, ci = e & 127;
        float v;
        if (ci < 64) v = ctr[ci];
        else         v = g_xt[((size_t)(b*NPTS) + nb[t])*FIN + (ci-64)] - ctr[ci-64];
        g_ee[(size_t)pos*EE_PER_POS + e] = v;
    }
}

// ---------------- conv1: 4 positions/block, thread = co ----------------------
__global__ __launch_bounds__(256) void k_conv1(const float* __restrict__ b1) {
    __shared__ float s_ee[4*EE_PER_POS];   // 40 KB, layout [p][t*128+ci]
    int pos0 = blockIdx.x * 4;
    for (int e = threadIdx.x; e < 4*EE_PER_POS; e += 256)
        s_ee[e] = g_ee[(size_t)pos0*EE_PER_POS + e];
    __syncthreads();
    int co = threadIdx.x;
    float acc[4][J1];
    #pragma unroll
    for (int p = 0; p < 4; p++)
        #pragma unroll
        for (int j = 0; j < J1; j++) acc[p][j] = 0.f;

    for (int ci = 0; ci < CI1; ci++) {
        float w[R1];
        #pragma unroll
        for (int r = 0; r < R1; r++) w[r] = g_w1t[(ci*R1 + r)*CO1 + co];
        #pragma unroll
        for (int p = 0; p < 4; p++) {
            const float* sp = s_ee + p*EE_PER_POS;
            float e_[KNN];
            #pragma unroll
            for (int t = 0; t < KNN; t++) e_[t] = sp[t*128 + ci];   // broadcast LDS
            #pragma unroll
            for (int j = 0; j < J1; j++) {
                float a = acc[p][j];
                #pragma unroll
                for (int r = 0; r < R1; r++) a = fmaf(w[r], e_[j+r], a);
                acc[p][j] = a;
            }
        }
    }
    float bias = b1[co];
    float s = 0.f, ss = 0.f;
    #pragma unroll
    for (int p = 0; p < 4; p++)
        #pragma unroll
        for (int j = 0; j < J1; j++) {
            float v = acc[p][j] + bias;
            g_h[(size_t)(pos0+p)*H_PER_POS + co*J1 + j] = v;
            s += v; ss += v*v;
        }
    atomicAdd(&g_s1[co], s);
    atomicAdd(&g_ss1[co], ss);
}

// ---------------- BN finalize ------------------------------------------------
__global__ void k_bnfin(const float* __restrict__ gam, const float* __restrict__ bet, int which) {
    int i = threadIdx.x;
    float s, ss, invcnt;
    if (which == 0) { s = g_s1[i]; ss = g_ss1[i]; invcnt = 1.f/163840.f; }
    else            { s = g_s2[i]; ss = g_ss2[i]; invcnt = 1.f/16384.f; }
    float mean = s*invcnt;
    float var  = ss*invcnt - mean*mean;
    float a = gam[i]*rsqrtf(var + BN_EPS);
    float c = bet[i] - mean*a;
    if (which == 0) { g_a1[i] = a; g_c1[i] = c; }
    else            { g_a2[i] = a; g_c2[i] = c; }
}

// ---------------- conv2: 8 positions/block, thread = 4co x 2pos --------------
__global__ __launch_bounds__(256) void k_conv2(const float* __restrict__ b2) {
    extern __shared__ float s_m[];         // 8 * 5120 floats = 160 KB
    __shared__ float s_a1[CO1], s_c1[CO1];
    int tid = threadIdx.x;
    s_a1[tid] = g_a1[tid];
    s_c1[tid] = g_c1[tid];
    __syncthreads();
    int pos0 = blockIdx.x * 8;
    // merge[..,0:20] = ee  (ee stored [t][ci] -> merge [ci][t])
    for (int e = tid; e < 8*EE_PER_POS; e += 256) {
        int p = e / EE_PER_POS; int q = e - p*EE_PER_POS;
        int t = q >> 7, ci = q & 127;
        s_m[p*KDIM2 + ci*T2 + t] = g_ee[(size_t)(pos0+p)*EE_PER_POS + q];
    }
    // merge[..,20:40] = inte = leaky(bn1(h)); reshape trick == identity on flat idx
    for (int e = tid; e < 8*H_PER_POS; e += 256) {
        int p = e / H_PER_POS; int q = e - p*H_PER_POS;
        int ci = q / KNN, t = q - ci*KNN;
        int cp = 2*ci + (t >= 10);
        float hv = g_h[(size_t)(pos0+p)*H_PER_POS + q];
        float v = fmaf(s_a1[cp], hv, s_c1[cp]);
        v = v > 0.f ? v : 0.01f*v;
        s_m[p*KDIM2 + ci*T2 + KNN + t] = v;
    }
    __syncthreads();

    int l = tid & 63, pg = tid >> 6;       // pg in 0..3 -> positions {2pg, 2pg+1}
    const float* m0p = s_m + (2*pg)*KDIM2;
    const float* m1p = s_m + (2*pg+1)*KDIM2;
    float acc[4][2];
    #pragma unroll
    for (int q2 = 0; q2 < 4; q2++) { acc[q2][0] = 0.f; acc[q2][1] = 0.f; }

    #pragma unroll 4
    for (int k = 0; k < KDIM2; k++) {
        float m0 = m0p[k], m1 = m1p[k];
        #pragma unroll
        for (int q2 = 0; q2 < 4; q2++) {
            float w = g_w2t[k*CO2 + l + 64*q2];
            acc[q2][0] = fmaf(w, m0, acc[q2][0]);
            acc[q2][1] = fmaf(w, m1, acc[q2][1]);
        }
    }
    #pragma unroll
    for (int q2 = 0; q2 < 4; q2++) {
        int co = l + 64*q2;
        float bias = b2[co];
        float v0 = acc[q2][0] + bias, v1 = acc[q2][1] + bias;
        g_out2[(size_t)(pos0 + 2*pg)*CO2 + co]     = v0;
        g_out2[(size_t)(pos0 + 2*pg + 1)*CO2 + co] = v1;
        atomicAdd(&g_s2[co],  v0 + v1);
        atomicAdd(&g_ss2[co], v0*v0 + v1*v1);
    }
}

// ---------------- BN2 + relu + final reshape --------------------------------
__global__ __launch_bounds__(256) void k_final(float* __restrict__ out) {
    __shared__ float s_t[32][257];
    __shared__ float sa[CO2], sc[CO2];
    int bx = blockIdx.x;
    int b = bx >> 6, n0 = (bx & 63)*32;
    int tid = threadIdx.x;
    sa[tid] = g_a2[tid]; sc[tid] = g_c2[tid];
    for (int e = tid; e < 32*256; e += 256) {
        int nn = e >> 8, co = e & 255;
        s_t[nn][co] = g_out2[(size_t)((b << 11) + n0 + nn)*CO2 + co];
    }
    __syncthreads();
    for (int e = tid; e < 32*256; e += 256) {
        int co = e >> 5, nn = e & 31;
        float v = fmaf(sa[co], s_t[nn][co], sc[co]);
        out[(size_t)b*(128*4096) + (co >> 1)*4096 + ((co & 1) << 11) + n0 + nn] = fmaxf(v, 0.f);
    }
}

// ---------------- launch -----------------------------------------------------
extern "C" void kernel_launch(void* const* d_in, const int* in_sizes, int n_in,
                              void* d_out, int out_size) {
    const float* x   = (const float*)d_in[0];
    const float* w1  = (const float*)d_in[1];
    const float* b1  = (const float*)d_in[2];
    const float* g1  = (const float*)d_in[3];
    const float* be1 = (const float*)d_in[4];
    const float* w2  = (const float*)d_in[5];
    const float* b2  = (const float*)d_in[6];
    const float* g2  = (const float*)d_in[7];
    const float* be2 = (const float*)d_in[8];
    float* out = (float*)d_out;

    cudaFuncSetAttribute(k_conv2, cudaFuncAttributeMaxDynamicSharedMemorySize, 8*KDIM2*4);

    k_zero<<<1, 256>>>();
    k_xt<<<NPOS, 64>>>(x);
    k_w1t<<<(CO1*CI1*R1 + 255)/256, 256>>>(w1);
    k_w2t<<<(CO2*CI1*T2 + 255)/256, 256>>>(w2);
    k_dist<<<dim3(NPTS/32, NPTS/32, BB), dim3(16,16)>>>();
    k_knn<<<NPOS, 256>>>();
    k_ee<<<NPOS, 256>>>();
    k_conv1<<<NPOS/4, 256>>>(b1);
    k_bnfin<<<1, 256>>>(g1, be1, 0);
    k_conv2<<<NPOS/8, 256, 8*KDIM2*4>>>(b2);
    k_bnfin<<<1, 256>>>(g2, be2, 1);
    k_final<<<BB*64, 256>>>(out);
}

// round 2
// speedup vs baseline: 2.0391x; 2.0391x over previous
#include <cuda_runtime.h>
#include <math.h>

#define BB   8
#define FIN  64
#define NPTS 2048
#define KNN  20
#define CI1  128
#define CO1  256
#define R1   11
#define J1   10
#define CO2  256
#define T2   40
#define NPOS  (BB*NPTS)          // 16384
#define H_PER_POS  (CO1*J1)      // 2560
#define K2P  3904                // reduced conv2 K: 64 ctr + 1280 nbv + 2560 inte
#define BN_EPS 1e-5f

// ---------------- scratch (device globals; no allocations allowed) ----------
__device__ float g_xt[NPOS*FIN];                 // [pos][d]
__device__ float g_sq[NPOS];
__device__ float g_dist[(size_t)NPOS*NPTS];      // [pos][j]   134 MB
__device__ int   g_idx[NPOS*KNN];
__device__ float g_w1b[64*R1*CO1];               // neighbor-half conv1 weights [(c*11+r)][co]
__device__ float g_wC[64*CO1];                   // folded central conv1 weights [c][co]
__device__ float4 g_w2v4[K2P*64];                // conv2 weights [(k'*64+l)] -> co = l,l+64,l+128,l+192
__device__ float g_h[(size_t)NPOS*H_PER_POS];    // [pos][co][j] 168 MB
__device__ float g_out2[(size_t)NPOS*CO2];       // [pos][co]
__device__ float g_s1[CO1], g_ss1[CO1], g_s2[CO2], g_ss2[CO2];
__device__ float g_a1[CO1], g_c1[CO1], g_a2[CO2], g_c2[CO2];

// ---------------- tiny prep kernels ----------------------------------------
__global__ void k_zero() {
    int t = threadIdx.x;
    g_s1[t] = 0.f; g_ss1[t] = 0.f; g_s2[t] = 0.f; g_ss2[t] = 0.f;
}

__global__ void k_xt(const float* __restrict__ x) {
    int pos = blockIdx.x;
    int b = pos >> 11, n = pos & (NPTS-1);
    int d = threadIdx.x;
    float v = x[((size_t)(b*FIN + d))*NPTS + n];
    g_xt[pos*FIN + d] = v;
    __shared__ float red[FIN];
    red[d] = v*v;
    __syncthreads();
    #pragma unroll
    for (int s = 32; s > 0; s >>= 1) {
        if (d < s) red[d] += red[d+s];
        __syncthreads();
    }
    if (d == 0) g_sq[pos] = red[0];
}

// conv1 weight prep: fold constant-across-t central terms.
// h[co][j] = sum_c ctr[c]*(Wa - Wb) + sum_c sum_r w1[co][64+c][r]*nbv[j+r][c]
__global__ void k_w1prep(const float* __restrict__ w1) {
    int e = blockIdx.x*256 + threadIdx.x;   // 64*256 threads
    int ci = e >> 8, co = e & 255;
    float sa = 0.f, sb = 0.f;
    #pragma unroll
    for (int r = 0; r < R1; r++) {
        sa += w1[co*(CI1*R1) + ci*R1 + r];
        float wb = w1[co*(CI1*R1) + (64+ci)*R1 + r];
        sb += wb;
        g_w1b[(ci*R1 + r)*CO1 + co] = wb;
    }
    g_wC[ci*CO1 + co] = sa - sb;
}

// conv2 weight prep into reduced-K float4 layout.
__global__ void k_w2v(const float* __restrict__ w2) {
    int e = blockIdx.x*256 + threadIdx.x;   // K2P*64 = 249856 threads
    int kp = e >> 6, l = e & 63;
    float v[4];
    #pragma unroll
    for (int q = 0; q < 4; q++) {
        int co = l + 64*q;
        float W;
        if (kp < 64) {
            int c = kp; W = 0.f;
            for (int t = 0; t < KNN; t++)
                W += w2[co*(CI1*T2) + c*T2 + t] - w2[co*(CI1*T2) + (64+c)*T2 + t];
        } else if (kp < 1344) {
            int u = kp - 64; int t = u >> 6, c = u & 63;
            W = w2[co*(CI1*T2) + (64+c)*T2 + t];
        } else {
            int u = kp - 1344; int ci = u/KNN, tp = u - ci*KNN;
            W = w2[co*(CI1*T2) + ci*T2 + KNN + tp];
        }
        v[q] = W;
    }
    g_w2v4[kp*64 + l] = make_float4(v[0], v[1], v[2], v[3]);
}

// ---------------- pairwise squared distances --------------------------------
__global__ __launch_bounds__(256) void k_dist() {
    __shared__ float si[32][65], sj[32][65];
    int b  = blockIdx.z;
    int i0 = blockIdx.y*32, j0 = blockIdx.x*32;
    int t  = threadIdx.y*16 + threadIdx.x;
    for (int e = t; e < 2048; e += 256) {
        int r = e >> 6, d = e & 63;
        si[r][d] = g_xt[((size_t)(b*NPTS) + i0 + r)*FIN + d];
        sj[r][d] = g_xt[((size_t)(b*NPTS) + j0 + r)*FIN + d];
    }
    __syncthreads();
    int iy = threadIdx.y, jx = threadIdx.x;
    float d00=0.f, d01=0.f, d10=0.f, d11=0.f;
    #pragma unroll
    for (int d = 0; d < 64; d++) {
        float a0 = si[iy][d],    a1 = si[iy+16][d];
        float c0 = sj[jx][d],    c1 = sj[jx+16][d];
        d00 += a0*c0; d01 += a0*c1; d10 += a1*c0; d11 += a1*c1;
    }
    float sqi0 = g_sq[b*NPTS + i0 + iy],   sqi1 = g_sq[b*NPTS + i0 + iy + 16];
    float sqj0 = g_sq[b*NPTS + j0 + jx],   sqj1 = g_sq[b*NPTS + j0 + jx + 16];
    size_t base0 = ((size_t)(b*NPTS) + i0 + iy)*NPTS + j0;
    size_t base1 = ((size_t)(b*NPTS) + i0 + iy + 16)*NPTS + j0;
    g_dist[base0 + jx]      = sqi0 + sqj0 - 2.f*d00;
    g_dist[base0 + jx + 16] = sqi0 + sqj1 - 2.f*d01;
    g_dist[base1 + jx]      = sqi1 + sqj0 - 2.f*d10;
    g_dist[base1 + jx + 16] = sqi1 + sqj1 - 2.f*d11;
}

// ---------------- top-20: per-warp segment selection + merge -----------------
__global__ __launch_bounds__(256) void k_knn() {
    __shared__ float cv[160];
    __shared__ int   cj[160];
    int pos = blockIdx.x;
    int i = pos & (NPTS-1);
    int tid = threadIdx.x;
    int warp = tid >> 5, lane = tid & 31;
    const float* row = g_dist + (size_t)pos*NPTS;
    int base = warp*256;
    float v[8];
    #pragma unroll
    for (int s = 0; s < 8; s++) {
        int j = base + lane + 32*s;
        float x = row[j];
        v[s] = (j == i) ? 1e30f : x;
    }
    // per-warp top-20 of its 256 elements (lexicographic (value, index))
    for (int kk = 0; kk < KNN; kk++) {
        float bv = v[0]; int bs = 0;
        #pragma unroll
        for (int s = 1; s < 8; s++) if (v[s] < bv) { bv = v[s]; bs = s; }
        int bj = base + lane + 32*bs;
        #pragma unroll
        for (int off = 16; off > 0; off >>= 1) {
            float ov = __shfl_down_sync(0xffffffffu, bv, off);
            int   oj = __shfl_down_sync(0xffffffffu, bj, off);
            if (ov < bv || (ov == bv && oj < bj)) { bv = ov; bj = oj; }
        }
        bv = __shfl_sync(0xffffffffu, bv, 0);
        bj = __shfl_sync(0xffffffffu, bj, 0);
        #pragma unroll
        for (int s = 0; s < 8; s++) if (base + lane + 32*s == bj) v[s] = 1e30f;
        if (lane == 0) { cv[warp*KNN + kk] = bv; cj[warp*KNN + kk] = bj; }
    }
    __syncthreads();
    // warp 0 merges 8*20 = 160 candidates
    if (warp == 0) {
        float mv[5]; int mj[5];
        #pragma unroll
        for (int s = 0; s < 5; s++) {
            int c = lane + 32*s;
            mv[s] = cv[c]; mj[s] = cj[c];
        }
        for (int kk = 0; kk < KNN; kk++) {
            float bv = mv[0]; int bj = mj[0];
            #pragma unroll
            for (int s = 1; s < 5; s++)
                if (mv[s] < bv || (mv[s] == bv && mj[s] < bj)) { bv = mv[s]; bj = mj[s]; }
            #pragma unroll
            for (int off = 16; off > 0; off >>= 1) {
                float ov = __shfl_down_sync(0xffffffffu, bv, off);
                int   oj = __shfl_down_sync(0xffffffffu, bj, off);
                if (ov < bv || (ov == bv && oj < bj)) { bv = ov; bj = oj; }
            }
            bv = __shfl_sync(0xffffffffu, bv, 0);
            bj = __shfl_sync(0xffffffffu, bj, 0);
            #pragma unroll
            for (int s = 0; s < 5; s++) if (mj[s] == bj) mv[s] = 1e30f;
            if (lane == 0) g_idx[pos*KNN + kk] = bj;
        }
    }
}

// ---------------- conv1: 4 pos/block, thread = co, central folded ------------
__global__ __launch_bounds__(256) void k_conv1(const float* __restrict__ b1) {
    __shared__ float s_nb[4*KNN*64];   // [p][t][c] 20 KB
    __shared__ float s_ct[4*64];
    __shared__ int   s_id[4*KNN];
    int pos0 = blockIdx.x * 4;
    int b = pos0 >> 11;
    int tid = threadIdx.x;
    if (tid < 4*KNN) s_id[tid] = g_idx[pos0*KNN + tid];
    s_ct[tid] = g_xt[pos0*FIN + tid];            // 256 = 4 pos * 64 contiguous
    __syncthreads();
    for (int e = tid; e < 4*KNN*64; e += 256) {
        int p = e / (KNN*64);
        int r = e - p*(KNN*64);
        int t = r >> 6, c = r & 63;
        s_nb[e] = g_xt[((size_t)(b << 11) + s_id[p*KNN + t])*FIN + c];
    }
    __syncthreads();

    int co = tid;
    float cacc[4] = {0.f, 0.f, 0.f, 0.f};
    #pragma unroll 8
    for (int c = 0; c < 64; c++) {
        float wc = g_wC[c*CO1 + co];
        #pragma unroll
        for (int p = 0; p < 4; p++) cacc[p] = fmaf(wc, s_ct[p*64 + c], cacc[p]);
    }
    float acc[4][J1];
    #pragma unroll
    for (int p = 0; p < 4; p++)
        #pragma unroll
        for (int j = 0; j < J1; j++) acc[p][j] = 0.f;

    for (int c = 0; c < 64; c++) {
        float w[R1];
        #pragma unroll
        for (int r = 0; r < R1; r++) w[r] = g_w1b[(c*R1 + r)*CO1 + co];
        #pragma unroll
        for (int p = 0; p < 4; p++) {
            float nb[KNN];
            #pragma unroll
            for (int t = 0; t < KNN; t++) nb[t] = s_nb[(p*KNN + t)*64 + c];  // broadcast
            #pragma unroll
            for (int j = 0; j < J1; j++) {
                float a = acc[p][j];
                #pragma unroll
                for (int r = 0; r < R1; r++) a = fmaf(w[r], nb[j+r], a);
                acc[p][j] = a;
            }
        }
    }
    float bias = b1[co];
    float s = 0.f, ss = 0.f;
    #pragma unroll
    for (int p = 0; p < 4; p++) {
        float cb = cacc[p] + bias;
        #pragma unroll
        for (int j = 0; j < J1; j++) {
            float v = acc[p][j] + cb;
            g_h[(size_t)(pos0+p)*H_PER_POS + co*J1 + j] = v;
            s += v; ss += v*v;
        }
    }
    atomicAdd(&g_s1[co], s);
    atomicAdd(&g_ss1[co], ss);
}

// ---------------- BN finalize ------------------------------------------------
__global__ void k_bnfin(const float* __restrict__ gam, const float* __restrict__ bet, int which) {
    int i = threadIdx.x;
    float s, ss, invcnt;
    if (which == 0) { s = g_s1[i]; ss = g_ss1[i]; invcnt = 1.f/163840.f; }
    else            { s = g_s2[i]; ss = g_ss2[i]; invcnt = 1.f/16384.f; }
    float mean = s*invcnt;
    float var  = ss*invcnt - mean*mean;
    float a = gam[i]*rsqrtf(var + BN_EPS);
    float c = bet[i] - mean*a;
    if (which == 0) { g_a1[i] = a; g_c1[i] = c; }
    else            { g_a2[i] = a; g_c2[i] = c; }
}

// ---------------- conv2: 8 pos/block, reduced K'=3904, float4 weights --------
__global__ __launch_bounds__(256) void k_conv2(const float* __restrict__ b2) {
    extern __shared__ float s_m[];         // 8 * 3904 floats = 124.9 KB
    __shared__ float s_a1[CO1], s_c1[CO1];
    __shared__ int   s_id[8*KNN];
    int tid = threadIdx.x;
    s_a1[tid] = g_a1[tid];
    s_c1[tid] = g_c1[tid];
    int pos0 = blockIdx.x * 8;
    int b = pos0 >> 11;
    if (tid < 8*KNN) s_id[tid] = g_idx[pos0*KNN + tid];
    __syncthreads();
    // build m: [0..63]=ctr, [64..1343]=nbv[t][c], [1344..3903]=inte(flat h order)
    for (int e = tid; e < 8*K2P; e += 256) {
        int p = e / K2P;
        int u = e - p*K2P;
        float v;
        if (u < 64) {
            v = g_xt[(pos0+p)*FIN + u];
        } else if (u < 1344) {
            int w = u - 64; int t = w >> 6, c = w & 63;
            v = g_xt[((size_t)(b << 11) + s_id[p*KNN + t])*FIN + c];
        } else {
            int q = u - 1344;
            int cp = q / J1;
            float hv = g_h[(size_t)(pos0+p)*H_PER_POS + q];
            float x = fmaf(s_a1[cp], hv, s_c1[cp]);
            v = x > 0.f ? x : 0.01f*x;
        }
        s_m[p*K2P + u] = v;
    }
    __syncthreads();

    int l = tid & 63, pg = tid >> 6;       // pg -> positions {2pg, 2pg+1}
    const float4* m0 = (const float4*)(s_m + (2*pg)*K2P);
    const float4* m1 = (const float4*)(s_m + (2*pg+1)*K2P);
    float acc[4][2];
    #pragma unroll
    for (int q = 0; q < 4; q++) { acc[q][0] = 0.f; acc[q][1] = 0.f; }

    #pragma unroll 2
    for (int kk = 0; kk < K2P/4; kk++) {
        float4 a4 = m0[kk], b4 = m1[kk];
        float am[4] = {a4.x, a4.y, a4.z, a4.w};
        float bm[4] = {b4.x, b4.y, b4.z, b4.w};
        #pragma unroll
        for (int d = 0; d < 4; d++) {
            float4 w = g_w2v4[(4*kk + d)*64 + l];
            acc[0][0] = fmaf(w.x, am[d], acc[0][0]); acc[0][1] = fmaf(w.x, bm[d], acc[0][1]);
            acc[1][0] = fmaf(w.y, am[d], acc[1][0]); acc[1][1] = fmaf(w.y, bm[d], acc[1][1]);
            acc[2][0] = fmaf(w.z, am[d], acc[2][0]); acc[2][1] = fmaf(w.z, bm[d], acc[2][1]);
            acc[3][0] = fmaf(w.w, am[d], acc[3][0]); acc[3][1] = fmaf(w.w, bm[d], acc[3][1]);
        }
    }
    #pragma unroll
    for (int q = 0; q < 4; q++) {
        int co = l + 64*q;
        float bias = b2[co];
        float v0 = acc[q][0] + bias, v1 = acc[q][1] + bias;
        g_out2[(size_t)(pos0 + 2*pg)*CO2 + co]     = v0;
        g_out2[(size_t)(pos0 + 2*pg + 1)*CO2 + co] = v1;
        atomicAdd(&g_s2[co],  v0 + v1);
        atomicAdd(&g_ss2[co], v0*v0 + v1*v1);
    }
}

// ---------------- BN2 + relu + final reshape --------------------------------
__global__ __launch_bounds__(256) void k_final(float* __restrict__ out) {
    __shared__ float s_t[32][257];
    __shared__ float sa[CO2], sc[CO2];
    int bx = blockIdx.x;
    int b = bx >> 6, n0 = (bx & 63)*32;
    int tid = threadIdx.x;
    sa[tid] = g_a2[tid]; sc[tid] = g_c2[tid];
    for (int e = tid; e < 32*256; e += 256) {
        int nn = e >> 8, co = e & 255;
        s_t[nn][co] = g_out2[(size_t)((b << 11) + n0 + nn)*CO2 + co];
    }
    __syncthreads();
    for (int e = tid; e < 32*256; e += 256) {
        int co = e >> 5, nn = e & 31;
        float v = fmaf(sa[co], s_t[nn][co], sc[co]);
        out[(size_t)b*(128*4096) + (co >> 1)*4096 + ((co & 1) << 11) + n0 + nn] = fmaxf(v, 0.f);
    }
}

// ---------------- launch -----------------------------------------------------
extern "C" void kernel_launch(void* const* d_in, const int* in_sizes, int n_in,
                              void* d_out, int out_size) {
    const float* x   = (const float*)d_in[0];
    const float* w1  = (const float*)d_in[1];
    const float* b1  = (const float*)d_in[2];
    const float* g1  = (const float*)d_in[3];
    const float* be1 = (const float*)d_in[4];
    const float* w2  = (const float*)d_in[5];
    const float* b2  = (const float*)d_in[6];
    const float* g2  = (const float*)d_in[7];
    const float* be2 = (const float*)d_in[8];
    float* out = (float*)d_out;

    cudaFuncSetAttribute(k_conv2, cudaFuncAttributeMaxDynamicSharedMemorySize, 8*K2P*4);

    k_zero<<<1, 256>>>();
    k_xt<<<NPOS, 64>>>(x);
    k_w1prep<<<64, 256>>>(w1);
    k_w2v<<<K2P*64/256, 256>>>(w2);
    k_dist<<<dim3(NPTS/32, NPTS/32, BB), dim3(16,16)>>>();
    k_knn<<<NPOS, 256>>>();
    k_conv1<<<NPOS/4, 256>>>(b1);
    k_bnfin<<<1, 256>>>(g1, be1, 0);
    k_conv2<<<NPOS/8, 256, 8*K2P*4>>>(b2);
    k_bnfin<<<1, 256>>>(g2, be2, 1);
    k_final<<<BB*64, 256>>>(out);
}

// round 3
// speedup vs baseline: 2.0448x; 1.0028x over previous
#include <cuda_runtime.h>
#include <math.h>

#define BB   8
#define FIN  64
#define NPTS 2048
#define KNN  20
#define CI1  128
#define CO1  256
#define R1   11
#define J1   10
#define CO2  256
#define T2   40
#define NPOS  (BB*NPTS)          // 16384
#define H_PER_POS  (CO1*J1)      // 2560
#define K2P  3904                // reduced conv2 K: 64 ctr + 1280 nbv + 2560 inte
#define BN_EPS 1e-5f

// ---------------- scratch (device globals; no allocations allowed) ----------
__device__ float g_xt[NPOS*FIN];                 // [pos][d]
__device__ float g_sq[NPOS];
__device__ float g_dist[(size_t)NPOS*NPTS];      // [pos][j]   134 MB
__device__ int   g_idx[NPOS*KNN];
__device__ float g_w1b[64*R1*CO1];               // neighbor-half conv1 weights [(c*11+r)][co]
__device__ float g_wC[64*CO1];                   // folded central conv1 weights [c][co]
__device__ float4 g_w2v4[K2P*64];                // conv2 weights [(k'*64+l)] -> co = l,l+64,l+128,l+192
__device__ float g_h[(size_t)NPOS*H_PER_POS];    // [pos][co][j] 168 MB
__device__ float g_out2[(size_t)NPOS*CO2];       // [pos][co]
__device__ float g_s1[CO1], g_ss1[CO1], g_s2[CO2], g_ss2[CO2];
__device__ float g_a1[CO1], g_c1[CO1], g_a2[CO2], g_c2[CO2];

// ---------------- tiny prep kernels ----------------------------------------
__global__ void k_zero() {
    int t = threadIdx.x;
    g_s1[t] = 0.f; g_ss1[t] = 0.f; g_s2[t] = 0.f; g_ss2[t] = 0.f;
}

__global__ void k_xt(const float* __restrict__ x) {
    int pos = blockIdx.x;
    int b = pos >> 11, n = pos & (NPTS-1);
    int d = threadIdx.x;
    float v = x[((size_t)(b*FIN + d))*NPTS + n];
    g_xt[pos*FIN + d] = v;
    __shared__ float red[FIN];
    red[d] = v*v;
    __syncthreads();
    #pragma unroll
    for (int s = 32; s > 0; s >>= 1) {
        if (d < s) red[d] += red[d+s];
        __syncthreads();
    }
    if (d == 0) g_sq[pos] = red[0];
}

// conv1 weight prep: fold constant-across-t central terms.
// h[co][j] = sum_c ctr[c]*(Wa - Wb) + sum_c sum_r w1[co][64+c][r]*nbv[j+r][c]
__global__ void k_w1prep(const float* __restrict__ w1) {
    int e = blockIdx.x*256 + threadIdx.x;   // 64*256 threads
    int ci = e >> 8, co = e & 255;
    float sa = 0.f, sb = 0.f;
    #pragma unroll
    for (int r = 0; r < R1; r++) {
        sa += w1[co*(CI1*R1) + ci*R1 + r];
        float wb = w1[co*(CI1*R1) + (64+ci)*R1 + r];
        sb += wb;
        g_w1b[(ci*R1 + r)*CO1 + co] = wb;
    }
    g_wC[ci*CO1 + co] = sa - sb;
}

// conv2 weight prep into reduced-K float4 layout.
__global__ void k_w2v(const float* __restrict__ w2) {
    int e = blockIdx.x*256 + threadIdx.x;   // K2P*64 = 249856 threads
    int kp = e >> 6, l = e & 63;
    float v[4];
    #pragma unroll
    for (int q = 0; q < 4; q++) {
        int co = l + 64*q;
        float W;
        if (kp < 64) {
            int c = kp; W = 0.f;
            for (int t = 0; t < KNN; t++)
                W += w2[co*(CI1*T2) + c*T2 + t] - w2[co*(CI1*T2) + (64+c)*T2 + t];
        } else if (kp < 1344) {
            int u = kp - 64; int t = u >> 6, c = u & 63;
            W = w2[co*(CI1*T2) + (64+c)*T2 + t];
        } else {
            int u = kp - 1344; int ci = u/KNN, tp = u - ci*KNN;
            W = w2[co*(CI1*T2) + ci*T2 + KNN + tp];
        }
        v[q] = W;
    }
    g_w2v4[kp*64 + l] = make_float4(v[0], v[1], v[2], v[3]);
}

// ---------------- pairwise squared distances --------------------------------
__global__ __launch_bounds__(256) void k_dist() {
    __shared__ float si[32][65], sj[32][65];
    int b  = blockIdx.z;
    int i0 = blockIdx.y*32, j0 = blockIdx.x*32;
    int t  = threadIdx.y*16 + threadIdx.x;
    for (int e = t; e < 2048; e += 256) {
        int r = e >> 6, d = e & 63;
        si[r][d] = g_xt[((size_t)(b*NPTS) + i0 + r)*FIN + d];
        sj[r][d] = g_xt[((size_t)(b*NPTS) + j0 + r)*FIN + d];
    }
    __syncthreads();
    int iy = threadIdx.y, jx = threadIdx.x;
    float d00=0.f, d01=0.f, d10=0.f, d11=0.f;
    #pragma unroll
    for (int d = 0; d < 64; d++) {
        float a0 = si[iy][d],    a1 = si[iy+16][d];
        float c0 = sj[jx][d],    c1 = sj[jx+16][d];
        d00 += a0*c0; d01 += a0*c1; d10 += a1*c0; d11 += a1*c1;
    }
    float sqi0 = g_sq[b*NPTS + i0 + iy],   sqi1 = g_sq[b*NPTS + i0 + iy + 16];
    float sqj0 = g_sq[b*NPTS + j0 + jx],   sqj1 = g_sq[b*NPTS + j0 + jx + 16];
    size_t base0 = ((size_t)(b*NPTS) + i0 + iy)*NPTS + j0;
    size_t base1 = ((size_t)(b*NPTS) + i0 + iy + 16)*NPTS + j0;
    g_dist[base0 + jx]      = sqi0 + sqj0 - 2.f*d00;
    g_dist[base0 + jx + 16] = sqi0 + sqj1 - 2.f*d01;
    g_dist[base1 + jx]      = sqi1 + sqj0 - 2.f*d10;
    g_dist[base1 + jx + 16] = sqi1 + sqj1 - 2.f*d11;
}

// ---------------- top-20: per-warp segment selection + merge -----------------
__global__ __launch_bounds__(256) void k_knn() {
    __shared__ float cv[160];
    __shared__ int   cj[160];
    int pos = blockIdx.x;
    int i = pos & (NPTS-1);
    int tid = threadIdx.x;
    int warp = tid >> 5, lane = tid & 31;
    const float* row = g_dist + (size_t)pos*NPTS;
    int base = warp*256;
    float v[8];
    #pragma unroll
    for (int s = 0; s < 8; s++) {
        int j = base + lane + 32*s;
        float x = row[j];
        v[s] = (j == i) ? 1e30f : x;
    }
    // per-warp top-20 of its 256 elements (lexicographic (value, index))
    for (int kk = 0; kk < KNN; kk++) {
        float bv = v[0]; int bs = 0;
        #pragma unroll
        for (int s = 1; s < 8; s++) if (v[s] < bv) { bv = v[s]; bs = s; }
        int bj = base + lane + 32*bs;
        #pragma unroll
        for (int off = 16; off > 0; off >>= 1) {
            float ov = __shfl_down_sync(0xffffffffu, bv, off);
            int   oj = __shfl_down_sync(0xffffffffu, bj, off);
            if (ov < bv || (ov == bv && oj < bj)) { bv = ov; bj = oj; }
        }
        bv = __shfl_sync(0xffffffffu, bv, 0);
        bj = __shfl_sync(0xffffffffu, bj, 0);
        #pragma unroll
        for (int s = 0; s < 8; s++) if (base + lane + 32*s == bj) v[s] = 1e30f;
        if (lane == 0) { cv[warp*KNN + kk] = bv; cj[warp*KNN + kk] = bj; }
    }
    __syncthreads();
    // warp 0 merges 8*20 = 160 candidates
    if (warp == 0) {
        float mv[5]; int mj[5];
        #pragma unroll
        for (int s = 0; s < 5; s++) {
            int c = lane + 32*s;
            mv[s] = cv[c]; mj[s] = cj[c];
        }
        for (int kk = 0; kk < KNN; kk++) {
            float bv = mv[0]; int bj = mj[0];
            #pragma unroll
            for (int s = 1; s < 5; s++)
                if (mv[s] < bv || (mv[s] == bv && mj[s] < bj)) { bv = mv[s]; bj = mj[s]; }
            #pragma unroll
            for (int off = 16; off > 0; off >>= 1) {
                float ov = __shfl_down_sync(0xffffffffu, bv, off);
                int   oj = __shfl_down_sync(0xffffffffu, bj, off);
                if (ov < bv || (ov == bv && oj < bj)) { bv = ov; bj = oj; }
            }
            bv = __shfl_sync(0xffffffffu, bv, 0);
            bj = __shfl_sync(0xffffffffu, bj, 0);
            #pragma unroll
            for (int s = 0; s < 5; s++) if (mj[s] == bj) mv[s] = 1e30f;
            if (lane == 0) g_idx[pos*KNN + kk] = bj;
        }
    }
}

// ---------------- conv1: 4 pos/block, thread = co, central folded ------------
__global__ __launch_bounds__(256) void k_conv1(const float* __restrict__ b1) {
    __shared__ float s_nb[4*KNN*64];   // [p][t][c] 20 KB
    __shared__ float s_ct[4*64];
    __shared__ int   s_id[4*KNN];
    int pos0 = blockIdx.x * 4;
    int b = pos0 >> 11;
    int tid = threadIdx.x;
    if (tid < 4*KNN) s_id[tid] = g_idx[pos0*KNN + tid];
    s_ct[tid] = g_xt[pos0*FIN + tid];            // 256 = 4 pos * 64 contiguous
    __syncthreads();
    for (int e = tid; e < 4*KNN*64; e += 256) {
        int p = e / (KNN*64);
        int r = e - p*(KNN*64);
        int t = r >> 6, c = r & 63;
        s_nb[e] = g_xt[((size_t)(b << 11) + s_id[p*KNN + t])*FIN + c];
    }
    __syncthreads();

    int co = tid;
    float cacc[4] = {0.f, 0.f, 0.f, 0.f};
    #pragma unroll 8
    for (int c = 0; c < 64; c++) {
        float wc = g_wC[c*CO1 + co];
        #pragma unroll
        for (int p = 0; p < 4; p++) cacc[p] = fmaf(wc, s_ct[p*64 + c], cacc[p]);
    }
    float acc[4][J1];
    #pragma unroll
    for (int p = 0; p < 4; p++)
        #pragma unroll
        for (int j = 0; j < J1; j++) acc[p][j] = 0.f;

    for (int c = 0; c < 64; c++) {
        float w[R1];
        #pragma unroll
        for (int r = 0; r < R1; r++) w[r] = g_w1b[(c*R1 + r)*CO1 + co];
        #pragma unroll
        for (int p = 0; p < 4; p++) {
            float nb[KNN];
            #pragma unroll
            for (int t = 0; t < KNN; t++) nb[t] = s_nb[(p*KNN + t)*64 + c];  // broadcast
            #pragma unroll
            for (int j = 0; j < J1; j++) {
                float a = acc[p][j];
                #pragma unroll
                for (int r = 0; r < R1; r++) a = fmaf(w[r], nb[j+r], a);
                acc[p][j] = a;
            }
        }
    }
    float bias = b1[co];
    float s = 0.f, ss = 0.f;
    #pragma unroll
    for (int p = 0; p < 4; p++) {
        float cb = cacc[p] + bias;
        #pragma unroll
        for (int j = 0; j < J1; j++) {
            float v = acc[p][j] + cb;
            g_h[(size_t)(pos0+p)*H_PER_POS + co*J1 + j] = v;
            s += v; ss += v*v;
        }
    }
    atomicAdd(&g_s1[co], s);
    atomicAdd(&g_ss1[co], ss);
}

// ---------------- BN finalize ------------------------------------------------
__global__ void k_bnfin(const float* __restrict__ gam, const float* __restrict__ bet, int which) {
    int i = threadIdx.x;
    float s, ss, invcnt;
    if (which == 0) { s = g_s1[i]; ss = g_ss1[i]; invcnt = 1.f/163840.f; }
    else            { s = g_s2[i]; ss = g_ss2[i]; invcnt = 1.f/16384.f; }
    float mean = s*invcnt;
    float var  = ss*invcnt - mean*mean;
    float a = gam[i]*rsqrtf(var + BN_EPS);
    float c = bet[i] - mean*a;
    if (which == 0) { g_a1[i] = a; g_c1[i] = c; }
    else            { g_a2[i] = a; g_c2[i] = c; }
}

// ---------------- conv2: 8 pos/block, reduced K'=3904, float4 weights --------
__global__ __launch_bounds__(256) void k_conv2(const float* __restrict__ b2) {
    extern __shared__ float s_m[];         // 8 * 3904 floats = 124.9 KB
    __shared__ float s_a1[CO1], s_c1[CO1];
    __shared__ int   s_id[8*KNN];
    int tid = threadIdx.x;
    s_a1[tid] = g_a1[tid];
    s_c1[tid] = g_c1[tid];
    int pos0 = blockIdx.x * 8;
    int b = pos0 >> 11;
    if (tid < 8*KNN) s_id[tid] = g_idx[pos0*KNN + tid];
    __syncthreads();
    // build m: [0..63]=ctr, [64..1343]=nbv[t][c], [1344..3903]=inte(flat h order)
    for (int e = tid; e < 8*K2P; e += 256) {
        int p = e / K2P;
        int u = e - p*K2P;
        float v;
        if (u < 64) {
            v = g_xt[(pos0+p)*FIN + u];
        } else if (u < 1344) {
            int w = u - 64; int t = w >> 6, c = w & 63;
            v = g_xt[((size_t)(b << 11) + s_id[p*KNN + t])*FIN + c];
        } else {
            int q = u - 1344;
            int cp = q / J1;
            float hv = g_h[(size_t)(pos0+p)*H_PER_POS + q];
            float x = fmaf(s_a1[cp], hv, s_c1[cp]);
            v = x > 0.f ? x : 0.01f*x;
        }
        s_m[p*K2P + u] = v;
    }
    __syncthreads();

    int l = tid & 63, pg = tid >> 6;       // pg -> positions {2pg, 2pg+1}
    const float4* m0 = (const float4*)(s_m + (2*pg)*K2P);
    const float4* m1 = (const float4*)(s_m + (2*pg+1)*K2P);
    float acc[4][2];
    #pragma unroll
    for (int q = 0; q < 4; q++) { acc[q][0] = 0.f; acc[q][1] = 0.f; }

    #pragma unroll 2
    for (int kk = 0; kk < K2P/4; kk++) {
        float4 a4 = m0[kk], b4 = m1[kk];
        float am[4] = {a4.x, a4.y, a4.z, a4.w};
        float bm[4] = {b4.x, b4.y, b4.z, b4.w};
        #pragma unroll
        for (int d = 0; d < 4; d++) {
            float4 w = g_w2v4[(4*kk + d)*64 + l];
            acc[0][0] = fmaf(w.x, am[d], acc[0][0]); acc[0][1] = fmaf(w.x, bm[d], acc[0][1]);
            acc[1][0] = fmaf(w.y, am[d], acc[1][0]); acc[1][1] = fmaf(w.y, bm[d], acc[1][1]);
            acc[2][0] = fmaf(w.z, am[d], acc[2][0]); acc[2][1] = fmaf(w.z, bm[d], acc[2][1]);
            acc[3][0] = fmaf(w.w, am[d], acc[3][0]); acc[3][1] = fmaf(w.w, bm[d], acc[3][1]);
        }
    }
    #pragma unroll
    for (int q = 0; q < 4; q++) {
        int co = l + 64*q;
        float bias = b2[co];
        float v0 = acc[q][0] + bias, v1 = acc[q][1] + bias;
        g_out2[(size_t)(pos0 + 2*pg)*CO2 + co]     = v0;
        g_out2[(size_t)(pos0 + 2*pg + 1)*CO2 + co] = v1;
        atomicAdd(&g_s2[co],  v0 + v1);
        atomicAdd(&g_ss2[co], v0*v0 + v1*v1);
    }
}

// ---------------- BN2 + relu + final reshape --------------------------------
__global__ __launch_bounds__(256) void k_final(float* __restrict__ out) {
    __shared__ float s_t[32][257];
    __shared__ float sa[CO2], sc[CO2];
    int bx = blockIdx.x;
    int b = bx >> 6, n0 = (bx & 63)*32;
    int tid = threadIdx.x;
    sa[tid] = g_a2[tid]; sc[tid] = g_c2[tid];
    for (int e = tid; e < 32*256; e += 256) {
        int nn = e >> 8, co = e & 255;
        s_t[nn][co] = g_out2[(size_t)((b << 11) + n0 + nn)*CO2 + co];
    }
    __syncthreads();
    for (int e = tid; e < 32*256; e += 256) {
        int co = e >> 5, nn = e & 31;
        float v = fmaf(sa[co], s_t[nn][co], sc[co]);
        out[(size_t)b*(128*4096) + (co >> 1)*4096 + ((co & 1) << 11) + n0 + nn] = fmaxf(v, 0.f);
    }
}

// ---------------- launch -----------------------------------------------------
extern "C" void kernel_launch(void* const* d_in, const int* in_sizes, int n_in,
                              void* d_out, int out_size) {
    const float* x   = (const float*)d_in[0];
    const float* w1  = (const float*)d_in[1];
    const float* b1  = (const float*)d_in[2];
    const float* g1  = (const float*)d_in[3];
    const float* be1 = (const float*)d_in[4];
    const float* w2  = (const float*)d_in[5];
    const float* b2  = (const float*)d_in[6];
    const float* g2  = (const float*)d_in[7];
    const float* be2 = (const float*)d_in[8];
    float* out = (float*)d_out;

    cudaFuncSetAttribute(k_conv2, cudaFuncAttributeMaxDynamicSharedMemorySize, 8*K2P*4);

    k_zero<<<1, 256>>>();
    k_xt<<<NPOS, 64>>>(x);
    k_w1prep<<<64, 256>>>(w1);
    k_w2v<<<K2P*64/256, 256>>>(w2);
    k_dist<<<dim3(NPTS/32, NPTS/32, BB), dim3(16,16)>>>();
    k_knn<<<NPOS, 256>>>();
    k_conv1<<<NPOS/4, 256>>>(b1);
    k_bnfin<<<1, 256>>>(g1, be1, 0);
    k_conv2<<<NPOS/8, 256, 8*K2P*4>>>(b2);
    k_bnfin<<<1, 256>>>(g2, be2, 1);
    k_final<<<BB*64, 256>>>(out);
}

// round 7
// speedup vs baseline: 4.8168x; 2.3557x over previous
#include <cuda_runtime.h>
#include <cuda_bf16.h>
#include <math.h>
#include <cstdint>

#define BB   8
#define FIN  64
#define NPTS 2048
#define KNN  20
#define R1   11
#define CO1  256
#define CO2  256
#define NPOS  (BB*NPTS)
#define BN_EPS 1e-5f

// ---------------- scratch ----------------------------------------------------
__device__ float g_xt[NPOS*FIN];
__device__ float g_sq[NPOS];
__device__ float g_dist[(size_t)NPOS*NPTS];
__device__ int   g_idx[NPOS*KNN];
__device__ __align__(16) unsigned short g_xhi[NPOS*FIN];
__device__ __align__(16) unsigned short g_xlo[NPOS*FIN];
__device__ __align__(16) unsigned short g_w1s[2*12*256*64];   // [sel][cc][co][c]
__device__ __align__(16) unsigned short g_w2s[(size_t)2*61*256*64]; // [sel][kc][co][c]
__device__ float g_h[(size_t)NPOS*2560];        // [pos][j][co]  j<10
__device__ float g_out2[(size_t)NPOS*CO2];      // [pos][co]
__device__ float g_s1[CO1], g_ss1[CO1], g_s2[CO2], g_ss2[CO2];
__device__ float g_a1[CO1], g_c1[CO1], g_a2[CO2], g_c2[CO2];

__device__ __forceinline__ unsigned short bfb(float x) {
    __nv_bfloat16 h = __float2bfloat16(x); return *reinterpret_cast<unsigned short*>(&h);
}
__device__ __forceinline__ float bfh(float x) { return __bfloat162float(__float2bfloat16(x)); }

__device__ __forceinline__ void mma16816(float* c, const uint32_t* a, uint32_t b0, uint32_t b1) {
    asm volatile("mma.sync.aligned.m16n8k16.row.col.f32.bf16.bf16.f32 "
        "{%0,%1,%2,%3}, {%4,%5,%6,%7}, {%8,%9}, {%0,%1,%2,%3};"
        : "+f"(c[0]), "+f"(c[1]), "+f"(c[2]), "+f"(c[3])
        : "r"(a[0]), "r"(a[1]), "r"(a[2]), "r"(a[3]), "r"(b0), "r"(b1));
}

// ---------------- prep -------------------------------------------------------
__global__ void k_zero() {
    int t = threadIdx.x;
    g_s1[t]=0.f; g_ss1[t]=0.f; g_s2[t]=0.f; g_ss2[t]=0.f;
}

__global__ void k_xt(const float* __restrict__ x) {
    int pos = blockIdx.x;
    int b = pos >> 11, n = pos & (NPTS-1);
    int d = threadIdx.x;
    float v = x[((size_t)(b*FIN + d))*NPTS + n];
    g_xt[pos*FIN + d] = v;
    g_xhi[pos*FIN + d] = bfb(v);
    g_xlo[pos*FIN + d] = bfb(v - bfh(v));
    __shared__ float red[FIN];
    red[d] = v*v;
    __syncthreads();
    #pragma unroll
    for (int s = 32; s > 0; s >>= 1) { if (d < s) red[d] += red[d+s]; __syncthreads(); }
    if (d == 0) g_sq[pos] = red[0];
}

// conv1 weights: 12 chunks (taps 0..10 on neighbor half, 11 = folded central)
__global__ void k_w1m(const float* __restrict__ w1) {
    int e = blockIdx.x*256 + threadIdx.x;   // 12*16384
    int cc = e >> 14, rem = e & 16383;
    int co = rem >> 6, c = rem & 63;
    float W;
    if (cc < 11) W = w1[co*1408 + (64+c)*R1 + cc];
    else {
        W = 0.f;
        for (int r = 0; r < R1; r++) W += w1[co*1408 + c*R1 + r] - w1[co*1408 + (64+c)*R1 + r];
    }
    g_w1s[(size_t)(cc*256 + co)*64 + c] = bfb(W);
    g_w1s[(size_t)(12*256*64) + (size_t)(cc*256 + co)*64 + c] = bfb(W - bfh(W));
}

// conv2 weights: k in [0,3904): [0,64)=ctr-fold, [64,1344)=nbv (t-major), [1344,3904)=inte (j-major)
__global__ void k_w2m(const float* __restrict__ w2) {
    int e = blockIdx.x*256 + threadIdx.x;   // 61*16384
    int kc = e >> 14, rem = e & 16383;
    int co = rem >> 6, c = rem & 63;
    int k = kc*64 + c;
    float W;
    if (k < 64) {
        W = 0.f;
        for (int t = 0; t < KNN; t++) W += w2[co*5120 + k*40 + t] - w2[co*5120 + (64+k)*40 + t];
    } else if (k < 1344) {
        int u = k - 64; int t = u >> 6, cx = u & 63;
        W = w2[co*5120 + (64+cx)*40 + t];
    } else {
        int u = k - 1344; int j = u >> 8, ch = u & 255;
        W = w2[co*5120 + (ch >> 1)*40 + 20 + (ch & 1)*10 + j];
    }
    g_w2s[(size_t)(kc*256 + co)*64 + c] = bfb(W);
    g_w2s[(size_t)(61*256*64) + (size_t)(kc*256 + co)*64 + c] = bfb(W - bfh(W));
}

// ---------------- distances + knn (unchanged) --------------------------------
__global__ __launch_bounds__(256) void k_dist() {
    __shared__ float si[32][65], sj[32][65];
    int b = blockIdx.z, i0 = blockIdx.y*32, j0 = blockIdx.x*32;
    int t = threadIdx.y*16 + threadIdx.x;
    for (int e = t; e < 2048; e += 256) {
        int r = e >> 6, d = e & 63;
        si[r][d] = g_xt[((size_t)(b*NPTS) + i0 + r)*FIN + d];
        sj[r][d] = g_xt[((size_t)(b*NPTS) + j0 + r)*FIN + d];
    }
    __syncthreads();
    int iy = threadIdx.y, jx = threadIdx.x;
    float d00=0.f, d01=0.f, d10=0.f, d11=0.f;
    #pragma unroll
    for (int d = 0; d < 64; d++) {
        float a0 = si[iy][d], a1 = si[iy+16][d];
        float c0 = sj[jx][d], c1 = sj[jx+16][d];
        d00 += a0*c0; d01 += a0*c1; d10 += a1*c0; d11 += a1*c1;
    }
    float sqi0 = g_sq[b*NPTS+i0+iy], sqi1 = g_sq[b*NPTS+i0+iy+16];
    float sqj0 = g_sq[b*NPTS+j0+jx], sqj1 = g_sq[b*NPTS+j0+jx+16];
    size_t b0 = ((size_t)(b*NPTS)+i0+iy)*NPTS + j0;
    size_t b1_ = ((size_t)(b*NPTS)+i0+iy+16)*NPTS + j0;
    g_dist[b0+jx] = sqi0+sqj0-2.f*d00;   g_dist[b0+jx+16] = sqi0+sqj1-2.f*d01;
    g_dist[b1_+jx] = sqi1+sqj0-2.f*d10;  g_dist[b1_+jx+16] = sqi1+sqj1-2.f*d11;
}

__global__ __launch_bounds__(256) void k_knn() {
    __shared__ float cv[160];
    __shared__ int   cj[160];
    int pos = blockIdx.x, i = pos & (NPTS-1);
    int tid = threadIdx.x, warp = tid >> 5, lane = tid & 31;
    const float* row = g_dist + (size_t)pos*NPTS;
    int base = warp*256;
    float v[8];
    #pragma unroll
    for (int s = 0; s < 8; s++) { int j = base+lane+32*s; float x = row[j]; v[s] = (j==i)?1e30f:x; }
    for (int kk = 0; kk < KNN; kk++) {
        float bv = v[0]; int bs = 0;
        #pragma unroll
        for (int s = 1; s < 8; s++) if (v[s] < bv) { bv = v[s]; bs = s; }
        int bj = base + lane + 32*bs;
        #pragma unroll
        for (int off = 16; off > 0; off >>= 1) {
            float ov = __shfl_down_sync(0xffffffffu, bv, off);
            int   oj = __shfl_down_sync(0xffffffffu, bj, off);
            if (ov < bv || (ov == bv && oj < bj)) { bv = ov; bj = oj; }
        }
        bv = __shfl_sync(0xffffffffu, bv, 0);
        bj = __shfl_sync(0xffffffffu, bj, 0);
        #pragma unroll
        for (int s = 0; s < 8; s++) if (base + lane + 32*s == bj) v[s] = 1e30f;
        if (lane == 0) { cv[warp*KNN+kk] = bv; cj[warp*KNN+kk] = bj; }
    }
    __syncthreads();
    if (warp == 0) {
        float mv[5]; int mj[5];
        #pragma unroll
        for (int s = 0; s < 5; s++) { int c = lane+32*s; mv[s] = cv[c]; mj[s] = cj[c]; }
        for (int kk = 0; kk < KNN; kk++) {
            float bv = mv[0]; int bj = mj[0];
            #pragma unroll
            for (int s = 1; s < 5; s++) if (mv[s] < bv || (mv[s] == bv && mj[s] < bj)) { bv = mv[s]; bj = mj[s]; }
            #pragma unroll
            for (int off = 16; off > 0; off >>= 1) {
                float ov = __shfl_down_sync(0xffffffffu, bv, off);
                int   oj = __shfl_down_sync(0xffffffffu, bj, off);
                if (ov < bv || (ov == bv && oj < bj)) { bv = ov; bj = oj; }
            }
            bv = __shfl_sync(0xffffffffu, bv, 0);
            bj = __shfl_sync(0xffffffffu, bj, 0);
            #pragma unroll
            for (int s = 0; s < 5; s++) if (mj[s] == bj) mv[s] = 1e30f;
            if (lane == 0) g_idx[pos*KNN + kk] = bj;
        }
    }
}

// ---------------- conv1: warp HMMA split-bf16 GEMM ---------------------------
// smem bytes: NBH 0(25344) NBL 25344 CTH 50688(1152) CTL 51840 BH 52992(18432)
//             BL 71424 BI 89856(1024) ID 90880(640) total 91520
#define C1_NBL 25344
#define C1_CTH 50688
#define C1_CTL 51840
#define C1_BH  52992
#define C1_BL  71424
#define C1_BI  89856
#define C1_ID  90880
#define C1_SZ  91520

__global__ __launch_bounds__(256) void k_conv1m(const float* __restrict__ b1) {
    extern __shared__ char sm[];
    int tid = threadIdx.x, wid = tid >> 5, lane = tid & 31;
    int pos0 = blockIdx.x*8, b = pos0 >> 11;
    int p = wid;                           // warp <-> position
    int* s_id = (int*)(sm + C1_ID);
    float* s_bi = (float*)(sm + C1_BI);

    if (tid < 160) s_id[tid] = g_idx[pos0*KNN + tid];
    s_bi[tid] = b1[tid];
    __syncthreads();
    // stage nb rows (160 rows x 64 bf16, padded to 72) hi/lo
    const uint4* xhi4 = (const uint4*)g_xhi;
    const uint4* xlo4 = (const uint4*)g_xlo;
    for (int e = tid; e < 1280; e += 256) {
        int row = e >> 3, u = e & 7;
        int gp = (b << 11) + s_id[row];
        *(uint4*)(sm + row*144 + u*16)          = xhi4[gp*8 + u];
        *(uint4*)(sm + C1_NBL + row*144 + u*16) = xlo4[gp*8 + u];
    }
    if (tid < 64) {
        int pp = tid >> 3, u = tid & 7;
        *(uint4*)(sm + C1_CTH + pp*144 + u*16) = xhi4[(pos0+pp)*8 + u];
        *(uint4*)(sm + C1_CTL + pp*144 + u*16) = xlo4[(pos0+pp)*8 + u];
    }

    int j0 = lane >> 2;
    int klo = (lane & 3) << 1;                 // k pair base within 8
    uint32_t bcol = (uint32_t)((lane >> 2)*144 + klo*2);

    for (int nh = 0; nh < 2; nh++) {
        float acc[16][4];
        #pragma unroll
        for (int nt = 0; nt < 16; nt++) { acc[nt][0]=0.f; acc[nt][1]=0.f; acc[nt][2]=0.f; acc[nt][3]=0.f; }
        for (int cc = 0; cc < 12; cc++) {
            __syncthreads();
            const uint4* wh = (const uint4*)(g_w1s) + (size_t)(cc*256 + nh*128)*8;
            const uint4* wl = (const uint4*)(g_w1s + 12*256*64) + (size_t)(cc*256 + nh*128)*8;
            #pragma unroll
            for (int i = 0; i < 4; i++) {
                int e = tid + 256*i;          // 1024 = 128co x 8
                int co = e >> 3, u = e & 7;
                *(uint4*)(sm + C1_BH + co*144 + u*16) = wh[e];
                *(uint4*)(sm + C1_BL + co*144 + u*16) = wl[e];
            }
            __syncthreads();
            const char *rp0h, *rp1h, *rp0l, *rp1l;
            if (cc < 11) {
                rp0h = sm + (p*20 + j0 + cc)*144;      rp1h = sm + (p*20 + j0 + 8 + cc)*144;
                rp0l = sm + C1_NBL + (p*20 + j0 + cc)*144; rp1l = sm + C1_NBL + (p*20 + j0 + 8 + cc)*144;
            } else {
                rp0h = sm + C1_CTH + p*144; rp1h = rp0h;
                rp0l = sm + C1_CTL + p*144; rp1l = rp0l;
            }
            #pragma unroll
            for (int s = 0; s < 4; s++) {
                int cb = s*16 + klo;
                uint32_t ah[4], al[4];
                ah[0] = *(const uint32_t*)(rp0h + cb*2);      ah[1] = *(const uint32_t*)(rp1h + cb*2);
                ah[2] = *(const uint32_t*)(rp0h + cb*2 + 16); ah[3] = *(const uint32_t*)(rp1h + cb*2 + 16);
                al[0] = *(const uint32_t*)(rp0l + cb*2);      al[1] = *(const uint32_t*)(rp1l + cb*2);
                al[2] = *(const uint32_t*)(rp0l + cb*2 + 16); al[3] = *(const uint32_t*)(rp1l + cb*2 + 16);
                #pragma unroll
                for (int nt = 0; nt < 16; nt++) {
                    uint32_t bo = bcol + nt*8*144 + s*32;
                    uint32_t bh0 = *(const uint32_t*)(sm + C1_BH + bo);
                    uint32_t bh1 = *(const uint32_t*)(sm + C1_BH + bo + 16);
                    uint32_t bl0 = *(const uint32_t*)(sm + C1_BL + bo);
                    uint32_t bl1 = *(const uint32_t*)(sm + C1_BL + bo + 16);
                    mma16816(acc[nt], ah, bh0, bh1);
                    mma16816(acc[nt], ah, bl0, bl1);
                    mma16816(acc[nt], al, bh0, bh1);
                }
            }
        }
        // epilogue: store j<10 rows, coalesced float2
        size_t hb = (size_t)(pos0 + p)*2560;
        #pragma unroll
        for (int nt = 0; nt < 16; nt++) {
            int co = nh*128 + nt*8 + klo;
            float2 v0; v0.x = acc[nt][0] + s_bi[co]; v0.y = acc[nt][1] + s_bi[co+1];
            *(float2*)&g_h[hb + j0*256 + co] = v0;
            if (j0 < 2) {
                float2 v1; v1.x = acc[nt][2] + s_bi[co]; v1.y = acc[nt][3] + s_bi[co+1];
                *(float2*)&g_h[hb + (j0+8)*256 + co] = v1;
            }
        }
    }
}

// ---------------- BN stats ---------------------------------------------------
__global__ __launch_bounds__(256) void k_stats1() {
    int tid = threadIdx.x;
    size_t base = (size_t)blockIdx.x*128*2560;
    float s = 0.f, ss = 0.f;
    for (int i = 0; i < 1280; i++) {
        float v = g_h[base + (size_t)i*256 + tid];
        s += v; ss += v*v;
    }
    atomicAdd(&g_s1[tid], s);
    atomicAdd(&g_ss1[tid], ss);
}
__global__ __launch_bounds__(256) void k_stats2() {
    int tid = threadIdx.x;
    size_t base = (size_t)blockIdx.x*128*256;
    float s = 0.f, ss = 0.f;
    for (int i = 0; i < 128; i++) {
        float v = g_out2[base + i*256 + tid];
        s += v; ss += v*v;
    }
    atomicAdd(&g_s2[tid], s);
    atomicAdd(&g_ss2[tid], ss);
}

__global__ void k_bnfin(const float* __restrict__ gam, const float* __restrict__ bet, int which) {
    int i = threadIdx.x;
    float s, ss, invcnt;
    if (which == 0) { s = g_s1[i]; ss = g_ss1[i]; invcnt = 1.f/163840.f; }
    else            { s = g_s2[i]; ss = g_ss2[i]; invcnt = 1.f/16384.f; }
    float mean = s*invcnt;
    float var  = ss*invcnt - mean*mean;
    float a = gam[i]*rsqrtf(var + BN_EPS);
    float c = bet[i] - mean*a;
    if (which == 0) { g_a1[i] = a; g_c1[i] = c; }
    else            { g_a2[i] = a; g_c2[i] = c; }
}

// ---------------- conv2: warp HMMA split-bf16 GEMM ---------------------------
// smem: AH 0(9216) AL 9216 BH 18432(36864) BL 55296 ID 92160(5120) A1 97280 C1 98304 BI 99328 SZ 100352
#define C2_AL 9216
#define C2_BH 18432
#define C2_BL 55296
#define C2_ID 92160
#define C2_A1 97280
#define C2_C1 98304
#define C2_BI 99328
#define C2_SZ 100352

__global__ __launch_bounds__(256) void k_conv2m(const float* __restrict__ b2) {
    extern __shared__ char sm[];
    int tid = threadIdx.x, wid = tid >> 5, lane = tid & 31;
    int pos0 = blockIdx.x*64, b = pos0 >> 11;
    int mstrip = wid & 3, nhalf = wid >> 2;
    int* s_id = (int*)(sm + C2_ID);
    float* s_a1 = (float*)(sm + C2_A1);
    float* s_c1 = (float*)(sm + C2_C1);
    float* s_bi = (float*)(sm + C2_BI);

    for (int e = tid; e < 1280; e += 256) s_id[e] = g_idx[pos0*KNN + e];
    s_a1[tid] = g_a1[tid]; s_c1[tid] = g_c1[tid]; s_bi[tid] = b2[tid];

    int j0 = lane >> 2;
    int klo = (lane & 3) << 1;
    uint32_t bcol = (uint32_t)((nhalf*128 + (lane >> 2))*144 + klo*2);
    int pl0 = mstrip*16 + j0;

    float acc[16][4];
    #pragma unroll
    for (int nt = 0; nt < 16; nt++) { acc[nt][0]=0.f; acc[nt][1]=0.f; acc[nt][2]=0.f; acc[nt][3]=0.f; }

    for (int kc = 0; kc < 61; kc++) {
        __syncthreads();
        // stage A chunk (64 pos x 64 k), split bf16
        #pragma unroll
        for (int i = 0; i < 16; i++) {
            int e = tid + 256*i;
            int pp = e >> 6, kk = e & 63;
            int k = kc*64 + kk;
            unsigned short hi, lo;
            if (k < 64) {
                hi = g_xhi[(pos0+pp)*64 + k]; lo = g_xlo[(pos0+pp)*64 + k];
            } else if (k < 1344) {
                int u = k - 64; int t = u >> 6, c = u & 63;
                int gp = (b << 11) + s_id[pp*KNN + t];
                hi = g_xhi[gp*64 + c]; lo = g_xlo[gp*64 + c];
            } else {
                int u = k - 1344;
                int ch = u & 255;
                float hv = g_h[(size_t)(pos0+pp)*2560 + u];
                float x = fmaf(s_a1[ch], hv, s_c1[ch]);
                float v = x > 0.f ? x : 0.01f*x;
                hi = bfb(v); lo = bfb(v - bfh(v));
            }
            *(unsigned short*)(sm + pp*144 + kk*2) = hi;
            *(unsigned short*)(sm + C2_AL + pp*144 + kk*2) = lo;
        }
        // stage B chunk (256 co x 64 k) hi/lo
        const uint4* wh = (const uint4*)(g_w2s) + (size_t)(kc*256)*8;
        const uint4* wl = (const uint4*)(g_w2s + (size_t)61*256*64) + (size_t)(kc*256)*8;
        #pragma unroll
        for (int i = 0; i < 8; i++) {
            int e = tid + 256*i;
            int co = e >> 3, u = e & 7;
            *(uint4*)(sm + C2_BH + co*144 + u*16) = wh[e];
            *(uint4*)(sm + C2_BL + co*144 + u*16) = wl[e];
        }
        __syncthreads();
        const char* rp0h = sm + pl0*144;
        const char* rp1h = sm + (pl0+8)*144;
        const char* rp0l = sm + C2_AL + pl0*144;
        const char* rp1l = sm + C2_AL + (pl0+8)*144;
        #pragma unroll
        for (int s = 0; s < 4; s++) {
            int cb = s*16 + klo;
            uint32_t ah[4], al[4];
            ah[0] = *(const uint32_t*)(rp0h + cb*2);      ah[1] = *(const uint32_t*)(rp1h + cb*2);
            ah[2] = *(const uint32_t*)(rp0h + cb*2 + 16); ah[3] = *(const uint32_t*)(rp1h + cb*2 + 16);
            al[0] = *(const uint32_t*)(rp0l + cb*2);      al[1] = *(const uint32_t*)(rp1l + cb*2);
            al[2] = *(const uint32_t*)(rp0l + cb*2 + 16); al[3] = *(const uint32_t*)(rp1l + cb*2 + 16);
            #pragma unroll
            for (int nt = 0; nt < 16; nt++) {
                uint32_t bo = bcol + nt*8*144 + s*32;
                uint32_t bh0 = *(const uint32_t*)(sm + C2_BH + bo);
                uint32_t bh1 = *(const uint32_t*)(sm + C2_BH + bo + 16);
                uint32_t bl0 = *(const uint32_t*)(sm + C2_BL + bo);
                uint32_t bl1 = *(const uint32_t*)(sm + C2_BL + bo + 16);
                mma16816(acc[nt], ah, bh0, bh1);
                mma16816(acc[nt], ah, bl0, bl1);
                mma16816(acc[nt], al, bh0, bh1);
            }
        }
    }
    // epilogue
    #pragma unroll
    for (int nt = 0; nt < 16; nt++) {
        int co = nhalf*128 + nt*8 + klo;
        float2 v0; v0.x = acc[nt][0] + s_bi[co]; v0.y = acc[nt][1] + s_bi[co+1];
        *(float2*)&g_out2[(size_t)(pos0 + pl0)*256 + co] = v0;
        float2 v1; v1.x = acc[nt][2] + s_bi[co]; v1.y = acc[nt][3] + s_bi[co+1];
        *(float2*)&g_out2[(size_t)(pos0 + pl0 + 8)*256 + co] = v1;
    }
}

// ---------------- BN2 + relu + final reshape --------------------------------
__global__ __launch_bounds__(256) void k_final(float* __restrict__ out) {
    __shared__ float s_t[32][257];
    __shared__ float sa[CO2], sc[CO2];
    int bx = blockIdx.x;
    int b = bx >> 6, n0 = (bx & 63)*32;
    int tid = threadIdx.x;
    sa[tid] = g_a2[tid]; sc[tid] = g_c2[tid];
    for (int e = tid; e < 32*256; e += 256) {
        int nn = e >> 8, co = e & 255;
        s_t[nn][co] = g_out2[(size_t)((b << 11) + n0 + nn)*256 + co];
    }
    __syncthreads();
    for (int e = tid; e < 32*256; e += 256) {
        int co = e >> 5, nn = e & 31;
        float v = fmaf(sa[co], s_t[nn][co], sc[co]);
        out[(size_t)b*(128*4096) + (co >> 1)*4096 + ((co & 1) << 11) + n0 + nn] = fmaxf(v, 0.f);
    }
}

// ---------------- launch -----------------------------------------------------
extern "C" void kernel_launch(void* const* d_in, const int* in_sizes, int n_in,
                              void* d_out, int out_size) {
    const float* x   = (const float*)d_in[0];
    const float* w1  = (const float*)d_in[1];
    const float* b1  = (const float*)d_in[2];
    const float* g1  = (const float*)d_in[3];
    const float* be1 = (const float*)d_in[4];
    const float* w2  = (const float*)d_in[5];
    const float* b2  = (const float*)d_in[6];
    const float* g2  = (const float*)d_in[7];
    const float* be2 = (const float*)d_in[8];
    float* out = (float*)d_out;

    cudaFuncSetAttribute(k_conv1m, cudaFuncAttributeMaxDynamicSharedMemorySize, C1_SZ);
    cudaFuncSetAttribute(k_conv2m, cudaFuncAttributeMaxDynamicSharedMemorySize, C2_SZ);

    k_zero<<<1, 256>>>();
    k_xt<<<NPOS, 64>>>(x);
    k_w1m<<<12*16384/256, 256>>>(w1);
    k_w2m<<<61*16384/256, 256>>>(w2);
    k_dist<<<dim3(NPTS/32, NPTS/32, BB), dim3(16,16)>>>();
    k_knn<<<NPOS, 256>>>();
    k_conv1m<<<NPOS/8, 256, C1_SZ>>>(b1);
    k_stats1<<<128, 256>>>();
    k_bnfin<<<1, 256>>>(g1, be1, 0);
    k_conv2m<<<NPOS/64, 256, C2_SZ>>>(b2);
    k_stats2<<<128, 256>>>();
    k_bnfin<<<1, 256>>>(g2, be2, 1);
    k_final<<<BB*64, 256>>>(out);
}

// round 9
// speedup vs baseline: 5.3930x; 1.1196x over previous
#include <cuda_runtime.h>
#include <cuda_bf16.h>
#include <math.h>
#include <cstdint>

#define BB   8
#define FIN  64
#define NPTS 2048
#define KNN  20
#define RTAP 11
#define CO1  256
#define CO2  256
#define NPOS  (BB*NPTS)
#define BN_EPS 1e-5f

// ---------------- scratch ----------------------------------------------------
__device__ float g_xt[NPOS*FIN];
__device__ float g_sq[NPOS];
__device__ float g_dist[(size_t)NPOS*NPTS];
__device__ int   g_idx[NPOS*KNN];
__device__ __align__(16) unsigned short g_xhi[NPOS*FIN];
__device__ __align__(16) unsigned short g_xlo[NPOS*FIN];
__device__ __align__(16) unsigned short g_w1s[2*12*256*64];        // [sel][cc][co][c]
__device__ __align__(16) unsigned short g_w2s[(size_t)2*61*256*64];// [sel][kc][co][c]
__device__ float g_h[(size_t)NPOS*2560];        // [pos][j][co]  j<10
__device__ float g_out2[(size_t)NPOS*CO2];      // [pos][co]
__device__ float g_s1[CO1], g_ss1[CO1], g_s2[CO2], g_ss2[CO2];
__device__ float g_a1[CO1], g_c1[CO1], g_a2[CO2], g_c2[CO2];

__device__ __forceinline__ unsigned short bfb(float x) {
    __nv_bfloat16 h = __float2bfloat16(x); return *reinterpret_cast<unsigned short*>(&h);
}
__device__ __forceinline__ float bfh(float x) { return __bfloat162float(__float2bfloat16(x)); }

__device__ __forceinline__ uint32_t s2u(const void* p) {
    uint32_t a; asm("{ .reg .u64 t; cvta.to.shared.u64 t, %1; cvt.u32.u64 %0, t; }" : "=r"(a) : "l"(p)); return a;
}
__device__ __forceinline__ void mma16816(float* c, const uint32_t* a, uint32_t b0, uint32_t b1) {
    asm volatile("mma.sync.aligned.m16n8k16.row.col.f32.bf16.bf16.f32 "
        "{%0,%1,%2,%3}, {%4,%5,%6,%7}, {%8,%9}, {%0,%1,%2,%3};"
        : "+f"(c[0]), "+f"(c[1]), "+f"(c[2]), "+f"(c[3])
        : "r"(a[0]), "r"(a[1]), "r"(a[2]), "r"(a[3]), "r"(b0), "r"(b1));
}
#define LDSM4(r0,r1,r2,r3,addr) \
    asm volatile("ldmatrix.sync.aligned.m8n8.x4.shared.b16 {%0,%1,%2,%3}, [%4];" \
        : "=r"(r0),"=r"(r1),"=r"(r2),"=r"(r3) : "r"(addr))
#define CP16(dst, src) asm volatile("cp.async.cg.shared.global [%0], [%1], 16;" :: "r"(dst), "l"(src))
#define CP_COMMIT()    asm volatile("cp.async.commit_group;" ::: "memory")
#define CP_WAIT1()     asm volatile("cp.async.wait_group 1;" ::: "memory")

// ---------------- prep -------------------------------------------------------
__global__ void k_zero() {
    int t = threadIdx.x;
    g_s1[t]=0.f; g_ss1[t]=0.f; g_s2[t]=0.f; g_ss2[t]=0.f;
}

__global__ void k_xt(const float* __restrict__ x) {
    int pos = blockIdx.x;
    int b = pos >> 11, n = pos & (NPTS-1);
    int d = threadIdx.x;
    float v = x[((size_t)(b*FIN + d))*NPTS + n];
    g_xt[pos*FIN + d] = v;
    g_xhi[pos*FIN + d] = bfb(v);
    g_xlo[pos*FIN + d] = bfb(v - bfh(v));
    __shared__ float red[FIN];
    red[d] = v*v;
    __syncthreads();
    #pragma unroll
    for (int s = 32; s > 0; s >>= 1) { if (d < s) red[d] += red[d+s]; __syncthreads(); }
    if (d == 0) g_sq[pos] = red[0];
}

__global__ void k_w1m(const float* __restrict__ w1) {
    int e = blockIdx.x*256 + threadIdx.x;   // 12*16384
    int cc = e >> 14, rem = e & 16383;
    int co = rem >> 6, c = rem & 63;
    float W;
    if (cc < 11) W = w1[co*1408 + (64+c)*RTAP + cc];
    else {
        W = 0.f;
        for (int r = 0; r < RTAP; r++) W += w1[co*1408 + c*RTAP + r] - w1[co*1408 + (64+c)*RTAP + r];
    }
    g_w1s[(size_t)(cc*256 + co)*64 + c] = bfb(W);
    g_w1s[(size_t)(12*256*64) + (size_t)(cc*256 + co)*64 + c] = bfb(W - bfh(W));
}

__global__ void k_w2m(const float* __restrict__ w2) {
    int e = blockIdx.x*256 + threadIdx.x;   // 61*16384
    int kc = e >> 14, rem = e & 16383;
    int co = rem >> 6, c = rem & 63;
    int k = kc*64 + c;
    float W;
    if (k < 64) {
        W = 0.f;
        for (int t = 0; t < KNN; t++) W += w2[co*5120 + k*40 + t] - w2[co*5120 + (64+k)*40 + t];
    } else if (k < 1344) {
        int u = k - 64; int t = u >> 6, cx = u & 63;
        W = w2[co*5120 + (64+cx)*40 + t];
    } else {
        int u = k - 1344; int j = u >> 8, ch = u & 255;
        W = w2[co*5120 + (ch >> 1)*40 + 20 + (ch & 1)*10 + j];
    }
    g_w2s[(size_t)(kc*256 + co)*64 + c] = bfb(W);
    g_w2s[(size_t)(61*256*64) + (size_t)(kc*256 + co)*64 + c] = bfb(W - bfh(W));
}

// ---------------- pairwise distances: 64x64 tile, 4x4/thread -----------------
__global__ __launch_bounds__(256) void k_dist() {
    __shared__ float sa[64][68], sb[64][68];   // d-major
    int b = blockIdx.z, i0 = blockIdx.y*64, j0 = blockIdx.x*64;
    int tid = threadIdx.x;
    int tx = tid & 15, ty = tid >> 4;
    const float4* xt4 = (const float4*)g_xt;
    for (int e = tid; e < 1024; e += 256) {
        int r = e >> 4, u = e & 15;
        float4 va = xt4[((size_t)(b*NPTS) + i0 + r)*16 + u];
        sa[u*4+0][r] = va.x; sa[u*4+1][r] = va.y; sa[u*4+2][r] = va.z; sa[u*4+3][r] = va.w;
        float4 vb = xt4[((size_t)(b*NPTS) + j0 + r)*16 + u];
        sb[u*4+0][r] = vb.x; sb[u*4+1][r] = vb.y; sb[u*4+2][r] = vb.z; sb[u*4+3][r] = vb.w;
    }
    __syncthreads();
    float acc[4][4];
    #pragma unroll
    for (int i = 0; i < 4; i++)
        #pragma unroll
        for (int j = 0; j < 4; j++) acc[i][j] = 0.f;
    #pragma unroll 4
    for (int d = 0; d < 64; d++) {
        float4 av = *(const float4*)&sa[d][ty*4];
        float4 bv = *(const float4*)&sb[d][tx*4];
        float a[4] = {av.x, av.y, av.z, av.w};
        float bq[4] = {bv.x, bv.y, bv.z, bv.w};
        #pragma unroll
        for (int i = 0; i < 4; i++)
            #pragma unroll
            for (int j = 0; j < 4; j++) acc[i][j] = fmaf(a[i], bq[j], acc[i][j]);
    }
    float sqj[4];
    #pragma unroll
    for (int j = 0; j < 4; j++) sqj[j] = g_sq[b*NPTS + j0 + tx*4 + j];
    #pragma unroll
    for (int i = 0; i < 4; i++) {
        float sqi = g_sq[b*NPTS + i0 + ty*4 + i];
        float4 o;
        o.x = sqi + sqj[0] - 2.f*acc[i][0];
        o.y = sqi + sqj[1] - 2.f*acc[i][1];
        o.z = sqi + sqj[2] - 2.f*acc[i][2];
        o.w = sqi + sqj[3] - 2.f*acc[i][3];
        *(float4*)&g_dist[((size_t)(b*NPTS) + i0 + ty*4 + i)*NPTS + j0 + tx*4] = o;
    }
}

// ---------------- top-20 (unchanged) -----------------------------------------
__global__ __launch_bounds__(256) void k_knn() {
    __shared__ float cv[160];
    __shared__ int   cj[160];
    int pos = blockIdx.x, i = pos & (NPTS-1);
    int tid = threadIdx.x, warp = tid >> 5, lane = tid & 31;
    const float* row = g_dist + (size_t)pos*NPTS;
    int base = warp*256;
    float v[8];
    #pragma unroll
    for (int s = 0; s < 8; s++) { int j = base+lane+32*s; float x = row[j]; v[s] = (j==i)?1e30f:x; }
    for (int kk = 0; kk < KNN; kk++) {
        float bv = v[0]; int bs = 0;
        #pragma unroll
        for (int s = 1; s < 8; s++) if (v[s] < bv) { bv = v[s]; bs = s; }
        int bj = base + lane + 32*bs;
        #pragma unroll
        for (int off = 16; off > 0; off >>= 1) {
            float ov = __shfl_down_sync(0xffffffffu, bv, off);
            int   oj = __shfl_down_sync(0xffffffffu, bj, off);
            if (ov < bv || (ov == bv && oj < bj)) { bv = ov; bj = oj; }
        }
        bv = __shfl_sync(0xffffffffu, bv, 0);
        bj = __shfl_sync(0xffffffffu, bj, 0);
        #pragma unroll
        for (int s = 0; s < 8; s++) if (base + lane + 32*s == bj) v[s] = 1e30f;
        if (lane == 0) { cv[warp*KNN+kk] = bv; cj[warp*KNN+kk] = bj; }
    }
    __syncthreads();
    if (warp == 0) {
        float mv[5]; int mj[5];
        #pragma unroll
        for (int s = 0; s < 5; s++) { int c = lane+32*s; mv[s] = cv[c]; mj[s] = cj[c]; }
        for (int kk = 0; kk < KNN; kk++) {
            float bv = mv[0]; int bj = mj[0];
            #pragma unroll
            for (int s = 1; s < 5; s++) if (mv[s] < bv || (mv[s] == bv && mj[s] < bj)) { bv = mv[s]; bj = mj[s]; }
            #pragma unroll
            for (int off = 16; off > 0; off >>= 1) {
                float ov = __shfl_down_sync(0xffffffffu, bv, off);
                int   oj = __shfl_down_sync(0xffffffffu, bj, off);
                if (ov < bv || (ov == bv && oj < bj)) { bv = ov; bj = oj; }
            }
            bv = __shfl_sync(0xffffffffu, bv, 0);
            bj = __shfl_sync(0xffffffffu, bj, 0);
            #pragma unroll
            for (int s = 0; s < 5; s++) if (mj[s] == bj) mv[s] = 1e30f;
            if (lane == 0) g_idx[pos*KNN + kk] = bj;
        }
    }
}

// ---------------- conv1: dense-M HMMA GEMM, cp.async B, ldmatrix -------------
#define C1_NBH 0
#define C1_NBL 40960
#define C1_CTH 81920
#define C1_CTL 83968
#define C1_B0  86016
#define C1_B1  118784
#define C1_BI  151552
#define C1_ID  152576
#define C1_SZ  153856

__global__ __launch_bounds__(640, 1) void k_conv1m(const float* __restrict__ b1) {
    extern __shared__ char sm[];
    uint32_t su = s2u(sm);
    int tid = threadIdx.x, wid = tid >> 5, lane = tid & 31;
    int pos0 = blockIdx.x*16, b = pos0 >> 11;
    int* s_id = (int*)(sm + C1_ID);
    float* s_bi = (float*)(sm + C1_BI);

    if (tid < 320) s_id[tid] = g_idx[pos0*KNN + tid];
    if (tid < 256) s_bi[tid] = b1[tid];
    __syncthreads();

    auto loadB = [&](int cc, int sel, uint32_t bufoff) {
        const char* wbase = (const char*)g_w1s + (size_t)sel*(12*256*64)*2;
        for (int e = tid; e < 2048; e += 640) {
            int co = e >> 3, u = e & 7;
            const char* src = wbase + (size_t)(cc*256 + co)*128 + u*16;
            uint32_t dst = su + bufoff + co*128 + ((u ^ (co & 7)) << 4);
            CP16(dst, src);
        }
    };
    loadB(0, 0, C1_B0); CP_COMMIT();
    loadB(0, 1, C1_B1); CP_COMMIT();

    // stage nb / ct tables (swizzled)
    const uint4* xhi4 = (const uint4*)g_xhi;
    const uint4* xlo4 = (const uint4*)g_xlo;
    for (int e = tid; e < 2560; e += 640) {
        int row = e >> 3, u = e & 7;
        int gp = (b << 11) + s_id[row];
        int sw = (u ^ (row & 7)) << 4;
        *(uint4*)(sm + C1_NBH + row*128 + sw) = xhi4[gp*8 + u];
        *(uint4*)(sm + C1_NBL + row*128 + sw) = xlo4[gp*8 + u];
    }
    if (tid < 128) {
        int row = tid >> 3, u = tid & 7;
        int sw = (u ^ (row & 7)) << 4;
        *(uint4*)(sm + C1_CTH + row*128 + sw) = xhi4[(pos0+row)*8 + u];
        *(uint4*)(sm + C1_CTL + row*128 + sw) = xlo4[(pos0+row)*8 + u];
    }

    int mh = wid >> 2, nq = wid & 3;        // 5 x 4
    int rr = (lane & 7) + ((lane >> 3) & 1)*8;
    int kx = lane >> 4;
    int Ra0 = mh*32 + rr, Ra1 = Ra0 + 16;
    int p0 = Ra0/10, jb0 = p0*20 + (Ra0 - p0*10);
    int p1 = Ra1/10, jb1 = p1*20 + (Ra1 - p1*10);
    int bn = lane & 7, bg = lane >> 3;      // B x4 lane decomp

    float acc[2][8][4];
    #pragma unroll
    for (int mt = 0; mt < 2; mt++)
        #pragma unroll
        for (int nt = 0; nt < 8; nt++)
            #pragma unroll
            for (int q = 0; q < 4; q++) acc[mt][nt][q] = 0.f;

    auto combo = [&](uint32_t atab, uint32_t bbase, int ar0, int ar1) {
        #pragma unroll
        for (int ks = 0; ks < 4; ks++) {
            uint32_t a0[4], a1[4];
            uint32_t ad0 = atab + ar0*128 + ((((ks<<1)|kx) ^ (ar0 & 7)) << 4);
            uint32_t ad1 = atab + ar1*128 + ((((ks<<1)|kx) ^ (ar1 & 7)) << 4);
            LDSM4(a0[0],a0[1],a0[2],a0[3], ad0);
            LDSM4(a1[0],a1[1],a1[2],a1[3], ad1);
            #pragma unroll
            for (int ng = 0; ng < 4; ng++) {
                int na = nq*64 + ng*16 + ((bg >> 1) << 3) + bn;
                int seg = (ks << 1) | (bg & 1);
                uint32_t bd = bbase + na*128 + ((seg ^ (na & 7)) << 4);
                uint32_t r0, r1, r2, r3;
                LDSM4(r0, r1, r2, r3, bd);
                mma16816(acc[0][2*ng],   a0, r0, r1);
                mma16816(acc[1][2*ng],   a1, r0, r1);
                mma16816(acc[0][2*ng+1], a0, r2, r3);
                mma16816(acc[1][2*ng+1], a1, r2, r3);
            }
        }
    };

    for (int cc = 0; cc < 12; cc++) {
        int ar0, ar1; uint32_t tabh, tabl;
        if (cc < 11) { ar0 = jb0 + cc; ar1 = jb1 + cc; tabh = su + C1_NBH; tabl = su + C1_NBL; }
        else         { ar0 = p0;       ar1 = p1;       tabh = su + C1_CTH; tabl = su + C1_CTL; }
        CP_WAIT1(); __syncthreads();
        combo(tabh, su + C1_B0, ar0, ar1);
        combo(tabl, su + C1_B0, ar0, ar1);
        __syncthreads();
        if (cc < 11) { loadB(cc+1, 0, C1_B0); CP_COMMIT(); }
        CP_WAIT1(); __syncthreads();
        combo(tabh, su + C1_B1, ar0, ar1);
        __syncthreads();
        if (cc < 11) { loadB(cc+1, 1, C1_B1); CP_COMMIT(); }
    }

    #pragma unroll
    for (int mt = 0; mt < 2; mt++) {
        int Ra = mh*32 + mt*16 + (lane >> 2);
        int Rb = Ra + 8;
        int pa = Ra/10, ja = Ra - pa*10;
        int pb = Rb/10, jb = Rb - pb*10;
        #pragma unroll
        for (int nt = 0; nt < 8; nt++) {
            int co = nq*64 + nt*8 + (lane & 3)*2;
            float b0 = s_bi[co], b1v = s_bi[co+1];
            float2 v0; v0.x = acc[mt][nt][0] + b0; v0.y = acc[mt][nt][1] + b1v;
            *(float2*)&g_h[(size_t)(pos0+pa)*2560 + ja*256 + co] = v0;
            float2 v1; v1.x = acc[mt][nt][2] + b0; v1.y = acc[mt][nt][3] + b1v;
            *(float2*)&g_h[(size_t)(pos0+pb)*2560 + jb*256 + co] = v1;
        }
    }
}

// ---------------- BN stats + finalize ----------------------------------------
__global__ __launch_bounds__(256) void k_stats1() {
    int tid = threadIdx.x;
    size_t base = (size_t)blockIdx.x*128*2560;
    float s = 0.f, ss = 0.f;
    for (int i = 0; i < 1280; i++) {
        float v = g_h[base + (size_t)i*256 + tid];
        s += v; ss += v*v;
    }
    atomicAdd(&g_s1[tid], s);
    atomicAdd(&g_ss1[tid], ss);
}
__global__ __launch_bounds__(256) void k_stats2() {
    int tid = threadIdx.x;
    size_t base = (size_t)blockIdx.x*128*256;
    float s = 0.f, ss = 0.f;
    for (int i = 0; i < 128; i++) {
        float v = g_out2[base + i*256 + tid];
        s += v; ss += v*v;
    }
    atomicAdd(&g_s2[tid], s);
    atomicAdd(&g_ss2[tid], ss);
}
__global__ void k_bnfin(const float* __restrict__ gam, const float* __restrict__ bet, int which) {
    int i = threadIdx.x;
    float s, ss, invcnt;
    if (which == 0) { s = g_s1[i]; ss = g_ss1[i]; invcnt = 1.f/163840.f; }
    else            { s = g_s2[i]; ss = g_ss2[i]; invcnt = 1.f/16384.f; }
    float mean = s*invcnt;
    float var  = ss*invcnt - mean*mean;
    float a = gam[i]*rsqrtf(var + BN_EPS);
    float c = bet[i] - mean*a;
    if (which == 0) { g_a1[i] = a; g_c1[i] = c; }
    else            { g_a2[i] = a; g_c2[i] = c; }
}

// ---------------- conv2: HMMA GEMM, cp.async B, ldmatrix ---------------------
#define C2_AH 0
#define C2_AL 8192
#define C2_B0 16384
#define C2_B1 49152
#define C2_ID 81920
#define C2_A1 87040
#define C2_C1 88064
#define C2_BI 89088
#define C2_SZ 90112

__global__ __launch_bounds__(256, 2) void k_conv2m(const float* __restrict__ b2) {
    extern __shared__ char sm[];
    uint32_t su = s2u(sm);
    int tid = threadIdx.x, wid = tid >> 5, lane = tid & 31;
    int pos0 = blockIdx.x*64, b = pos0 >> 11;
    int* s_id = (int*)(sm + C2_ID);
    float* s_a1 = (float*)(sm + C2_A1);
    float* s_c1 = (float*)(sm + C2_C1);
    float* s_bi = (float*)(sm + C2_BI);

    for (int e = tid; e < 1280; e += 256) s_id[e] = g_idx[pos0*KNN + e];
    s_a1[tid] = g_a1[tid]; s_c1[tid] = g_c1[tid]; s_bi[tid] = b2[tid];
    __syncthreads();

    auto loadB = [&](int kc, int sel, uint32_t bufoff) {
        const char* wbase = (const char*)g_w2s + (size_t)sel*((size_t)61*256*64)*2;
        for (int e = tid; e < 2048; e += 256) {
            int co = e >> 3, u = e & 7;
            const char* src = wbase + (size_t)(kc*256 + co)*128 + u*16;
            uint32_t dst = su + bufoff + co*128 + ((u ^ (co & 7)) << 4);
            CP16(dst, src);
        }
    };
    loadB(0, 0, C2_B0); CP_COMMIT();
    loadB(0, 1, C2_B1); CP_COMMIT();

    int mh = wid >> 2, nq = wid & 3;          // 2 x 4
    int rr = (lane & 7) + ((lane >> 3) & 1)*8;
    int kx = lane >> 4;
    int Ra0 = mh*32 + rr, Ra1 = Ra0 + 16;
    int bn = lane & 7, bg = lane >> 3;

    float acc[2][8][4];
    #pragma unroll
    for (int mt = 0; mt < 2; mt++)
        #pragma unroll
        for (int nt = 0; nt < 8; nt++)
            #pragma unroll
            for (int q = 0; q < 4; q++) acc[mt][nt][q] = 0.f;

    auto combo = [&](uint32_t atab, uint32_t bbase) {
        #pragma unroll
        for (int ks = 0; ks < 4; ks++) {
            uint32_t a0[4], a1[4];
            uint32_t ad0 = atab + Ra0*128 + ((((ks<<1)|kx) ^ (Ra0 & 7)) << 4);
            uint32_t ad1 = atab + Ra1*128 + ((((ks<<1)|kx) ^ (Ra1 & 7)) << 4);
            LDSM4(a0[0],a0[1],a0[2],a0[3], ad0);
            LDSM4(a1[0],a1[1],a1[2],a1[3], ad1);
            #pragma unroll
            for (int ng = 0; ng < 4; ng++) {
                int na = nq*64 + ng*16 + ((bg >> 1) << 3) + bn;
                int seg = (ks << 1) | (bg & 1);
                uint32_t bd = bbase + na*128 + ((seg ^ (na & 7)) << 4);
                uint32_t r0, r1, r2, r3;
                LDSM4(r0, r1, r2, r3, bd);
                mma16816(acc[0][2*ng],   a0, r0, r1);
                mma16816(acc[1][2*ng],   a1, r0, r1);
                mma16816(acc[0][2*ng+1], a0, r2, r3);
                mma16816(acc[1][2*ng+1], a1, r2, r3);
            }
        }
    };

    for (int kc = 0; kc < 61; kc++) {
        // build A chunk (both precisions), swizzled
        for (int e = tid; e < 4096; e += 256) {
            int pp = e >> 6, kk = e & 63;
            int k = kc*64 + kk;
            unsigned short hi, lo;
            if (k < 64) {
                hi = g_xhi[(pos0+pp)*64 + k]; lo = g_xlo[(pos0+pp)*64 + k];
            } else if (k < 1344) {
                int u = k - 64; int t = u >> 6, c = u & 63;
                int gp = (b << 11) + s_id[pp*KNN + t];
                hi = g_xhi[gp*64 + c]; lo = g_xlo[gp*64 + c];
            } else {
                int u = k - 1344;
                int ch = u & 255;
                float hv = g_h[(size_t)(pos0+pp)*2560 + u];
                float x = fmaf(s_a1[ch], hv, s_c1[ch]);
                float v = x > 0.f ? x : 0.01f*x;
                hi = bfb(v); lo = bfb(v - bfh(v));
            }
            int off = pp*128 + (((kk >> 3) ^ (pp & 7)) << 4) + (kk & 7)*2;
            *(unsigned short*)(sm + C2_AH + off) = hi;
            *(unsigned short*)(sm + C2_AL + off) = lo;
        }
        CP_WAIT1(); __syncthreads();
        combo(su + C2_AH, su + C2_B0);
        combo(su + C2_AL, su + C2_B0);
        __syncthreads();
        if (kc < 60) { loadB(kc+1, 0, C2_B0); CP_COMMIT(); }
        CP_WAIT1(); __syncthreads();
        combo(su + C2_AH, su + C2_B1);
        __syncthreads();
        if (kc < 60) { loadB(kc+1, 1, C2_B1); CP_COMMIT(); }
    }

    #pragma unroll
    for (int mt = 0; mt < 2; mt++) {
        int Ra = mh*32 + mt*16 + (lane >> 2);
        int Rb = Ra + 8;
        #pragma unroll
        for (int nt = 0; nt < 8; nt++) {
            int co = nq*64 + nt*8 + (lane & 3)*2;
            float b0 = s_bi[co], b1v = s_bi[co+1];
            float2 v0; v0.x = acc[mt][nt][0] + b0; v0.y = acc[mt][nt][1] + b1v;
            *(float2*)&g_out2[(size_t)(pos0+Ra)*256 + co] = v0;
            float2 v1; v1.x = acc[mt][nt][2] + b0; v1.y = acc[mt][nt][3] + b1v;
            *(float2*)&g_out2[(size_t)(pos0+Rb)*256 + co] = v1;
        }
    }
}

// ---------------- BN2 + relu + final reshape ---------------------------------
__global__ __launch_bounds__(256) void k_final(float* __restrict__ out) {
    __shared__ float s_t[32][257];
    __shared__ float sa[CO2], sc[CO2];
    int bx = blockIdx.x;
    int b = bx >> 6, n0 = (bx & 63)*32;
    int tid = threadIdx.x;
    sa[tid] = g_a2[tid]; sc[tid] = g_c2[tid];
    for (int e = tid; e < 32*256; e += 256) {
        int nn = e >> 8, co = e & 255;
        s_t[nn][co] = g_out2[(size_t)((b << 11) + n0 + nn)*256 + co];
    }
    __syncthreads();
    for (int e = tid; e < 32*256; e += 256) {
        int co = e >> 5, nn = e & 31;
        float v = fmaf(sa[co], s_t[nn][co], sc[co]);
        out[(size_t)b*(128*4096) + (co >> 1)*4096 + ((co & 1) << 11) + n0 + nn] = fmaxf(v, 0.f);
    }
}

// ---------------- launch -----------------------------------------------------
extern "C" void kernel_launch(void* const* d_in, const int* in_sizes, int n_in,
                              void* d_out, int out_size) {
    const float* x   = (const float*)d_in[0];
    const float* w1  = (const float*)d_in[1];
    const float* b1  = (const float*)d_in[2];
    const float* g1  = (const float*)d_in[3];
    const float* be1 = (const float*)d_in[4];
    const float* w2  = (const float*)d_in[5];
    const float* b2  = (const float*)d_in[6];
    const float* g2  = (const float*)d_in[7];
    const float* be2 = (const float*)d_in[8];
    float* out = (float*)d_out;

    cudaFuncSetAttribute(k_conv1m, cudaFuncAttributeMaxDynamicSharedMemorySize, C1_SZ);
    cudaFuncSetAttribute(k_conv2m, cudaFuncAttributeMaxDynamicSharedMemorySize, C2_SZ);

    k_zero<<<1, 256>>>();
    k_xt<<<NPOS, 64>>>(x);
    k_w1m<<<12*16384/256, 256>>>(w1);
    k_w2m<<<61*16384/256, 256>>>(w2);
    k_dist<<<dim3(NPTS/64, NPTS/64, BB), 256>>>();
    k_knn<<<NPOS, 256>>>();
    k_conv1m<<<NPOS/16, 640, C1_SZ>>>(b1);
    k_stats1<<<128, 256>>>();
    k_bnfin<<<1, 256>>>(g1, be1, 0);
    k_conv2m<<<NPOS/64, 256, C2_SZ>>>(b2);
    k_stats2<<<128, 256>>>();
    k_bnfin<<<1, 256>>>(g2, be2, 1);
    k_final<<<BB*64, 256>>>(out);
}

// round 13
// speedup vs baseline: 8.6147x; 1.5974x over previous
#include <cuda_runtime.h>
#include <cuda_fp16.h>
#include <math.h>
#include <cstdint>

#define BB   8
#define FIN  64
#define NPTS 2048
#define KNN  20
#define RTAP 11
#define CO1  256
#define CO2  256
#define NPOS  (BB*NPTS)
#define BN_EPS 1e-5f

// ---------------- scratch ----------------------------------------------------
__device__ float g_xt[NPOS*FIN];
__device__ float g_sq[NPOS];
__device__ float g_dist[(size_t)NPOS*NPTS];
__device__ int   g_idx[NPOS*KNN];
__device__ __align__(16) unsigned short g_xh[NPOS*FIN];            // fp16(x)
__device__ __align__(16) unsigned short g_w1s[2*12*256*64];        // [sel][cc][co][c] fp16 hi/lo
__device__ __align__(16) unsigned short g_w2s[(size_t)2*61*256*64];// [sel][kc][co][c] fp16 hi/lo
__device__ float g_h[(size_t)NPOS*2560];        // [pos][j][co]  j<10
__device__ float g_out2[(size_t)NPOS*CO2];      // [pos][co]
__device__ float g_s1[CO1], g_ss1[CO1], g_s2[CO2], g_ss2[CO2];
__device__ float g_a1[CO1], g_c1[CO1], g_a2[CO2], g_c2[CO2];

__device__ __forceinline__ unsigned short fhb(float x) {
    __half h = __float2half_rn(x); return *reinterpret_cast<unsigned short*>(&h);
}
__device__ __forceinline__ float fhf(float x) { return __half2float(__float2half_rn(x)); }

__device__ __forceinline__ uint32_t s2u(const void* p) {
    uint32_t a; asm("{ .reg .u64 t; cvta.to.shared.u64 t, %1; cvt.u32.u64 %0, t; }" : "=r"(a) : "l"(p)); return a;
}
__device__ __forceinline__ void mma16816(float* c, const uint32_t* a, uint32_t b0, uint32_t b1) {
    asm volatile("mma.sync.aligned.m16n8k16.row.col.f32.f16.f16.f32 "
        "{%0,%1,%2,%3}, {%4,%5,%6,%7}, {%8,%9}, {%0,%1,%2,%3};"
        : "+f"(c[0]), "+f"(c[1]), "+f"(c[2]), "+f"(c[3])
        : "r"(a[0]), "r"(a[1]), "r"(a[2]), "r"(a[3]), "r"(b0), "r"(b1));
}
#define LDSM4(r0,r1,r2,r3,addr) \
    asm volatile("ldmatrix.sync.aligned.m8n8.x4.shared.b16 {%0,%1,%2,%3}, [%4];" \
        : "=r"(r0),"=r"(r1),"=r"(r2),"=r"(r3) : "r"(addr))
#define CP16(dst, src) asm volatile("cp.async.cg.shared.global [%0], [%1], 16;" :: "r"(dst), "l"(src))
#define CP_COMMIT()    asm volatile("cp.async.commit_group;" ::: "memory")
#define CP_WAIT1()     asm volatile("cp.async.wait_group 1;" ::: "memory")

// ---------------- prep -------------------------------------------------------
__global__ void k_zero() {
    int t = threadIdx.x;
    g_s1[t]=0.f; g_ss1[t]=0.f; g_s2[t]=0.f; g_ss2[t]=0.f;
}

__global__ void k_xt(const float* __restrict__ x) {
    int pos = blockIdx.x;
    int b = pos >> 11, n = pos & (NPTS-1);
    int d = threadIdx.x;
    float v = x[((size_t)(b*FIN + d))*NPTS + n];
    g_xt[pos*FIN + d] = v;
    g_xh[pos*FIN + d] = fhb(v);
    __shared__ float red[FIN];
    red[d] = v*v;
    __syncthreads();
    #pragma unroll
    for (int s = 32; s > 0; s >>= 1) { if (d < s) red[d] += red[d+s]; __syncthreads(); }
    if (d == 0) g_sq[pos] = red[0];
}

__global__ void k_w1m(const float* __restrict__ w1) {
    int e = blockIdx.x*256 + threadIdx.x;   // 12*16384
    int cc = e >> 14, rem = e & 16383;
    int co = rem >> 6, c = rem & 63;
    float W;
    if (cc < 11) W = w1[co*1408 + (64+c)*RTAP + cc];
    else {
        W = 0.f;
        for (int r = 0; r < RTAP; r++) W += w1[co*1408 + c*RTAP + r] - w1[co*1408 + (64+c)*RTAP + r];
    }
    g_w1s[(size_t)(cc*256 + co)*64 + c] = fhb(W);
    g_w1s[(size_t)(12*256*64) + (size_t)(cc*256 + co)*64 + c] = fhb(W - fhf(W));
}

__global__ void k_w2m(const float* __restrict__ w2) {
    int e = blockIdx.x*256 + threadIdx.x;   // 61*16384
    int kc = e >> 14, rem = e & 16383;
    int co = rem >> 6, c = rem & 63;
    int k = kc*64 + c;
    float W;
    if (k < 64) {
        W = 0.f;
        for (int t = 0; t < KNN; t++) W += w2[co*5120 + k*40 + t] - w2[co*5120 + (64+k)*40 + t];
    } else if (k < 1344) {
        int u = k - 64; int t = u >> 6, cx = u & 63;
        W = w2[co*5120 + (64+cx)*40 + t];
    } else {
        int u = k - 1344; int j = u >> 8, ch = u & 255;
        W = w2[co*5120 + (ch >> 1)*40 + 20 + (ch & 1)*10 + j];
    }
    g_w2s[(size_t)(kc*256 + co)*64 + c] = fhb(W);
    g_w2s[(size_t)(61*256*64) + (size_t)(kc*256 + co)*64 + c] = fhb(W - fhf(W));
}

// ---------------- pairwise distances: 64x64 tile, 4x4/thread -----------------
__global__ __launch_bounds__(256) void k_dist() {
    __shared__ float sa[64][68], sb[64][68];   // d-major
    int b = blockIdx.z, i0 = blockIdx.y*64, j0 = blockIdx.x*64;
    int tid = threadIdx.x;
    int tx = tid & 15, ty = tid >> 4;
    const float4* xt4 = (const float4*)g_xt;
    for (int e = tid; e < 1024; e += 256) {
        int r = e >> 4, u = e & 15;
        float4 va = xt4[((size_t)(b*NPTS) + i0 + r)*16 + u];
        sa[u*4+0][r] = va.x; sa[u*4+1][r] = va.y; sa[u*4+2][r] = va.z; sa[u*4+3][r] = va.w;
        float4 vb = xt4[((size_t)(b*NPTS) + j0 + r)*16 + u];
        sb[u*4+0][r] = vb.x; sb[u*4+1][r] = vb.y; sb[u*4+2][r] = vb.z; sb[u*4+3][r] = vb.w;
    }
    __syncthreads();
    float acc[4][4];
    #pragma unroll
    for (int i = 0; i < 4; i++)
        #pragma unroll
        for (int j = 0; j < 4; j++) acc[i][j] = 0.f;
    #pragma unroll 4
    for (int d = 0; d < 64; d++) {
        float4 av = *(const float4*)&sa[d][ty*4];
        float4 bv = *(const float4*)&sb[d][tx*4];
        float a[4] = {av.x, av.y, av.z, av.w};
        float bq[4] = {bv.x, bv.y, bv.z, bv.w};
        #pragma unroll
        for (int i = 0; i < 4; i++)
            #pragma unroll
            for (int j = 0; j < 4; j++) acc[i][j] = fmaf(a[i], bq[j], acc[i][j]);
    }
    float sqj[4];
    #pragma unroll
    for (int j = 0; j < 4; j++) sqj[j] = g_sq[b*NPTS + j0 + tx*4 + j];
    #pragma unroll
    for (int i = 0; i < 4; i++) {
        float sqi = g_sq[b*NPTS + i0 + ty*4 + i];
        float4 o;
        o.x = sqi + sqj[0] - 2.f*acc[i][0];
        o.y = sqi + sqj[1] - 2.f*acc[i][1];
        o.z = sqi + sqj[2] - 2.f*acc[i][2];
        o.w = sqi + sqj[3] - 2.f*acc[i][3];
        *(float4*)&g_dist[((size_t)(b*NPTS) + i0 + ty*4 + i)*NPTS + j0 + tx*4] = o;
    }
}

// ---------------- top-20 (unchanged) -----------------------------------------
__global__ __launch_bounds__(256) void k_knn() {
    __shared__ float cv[160];
    __shared__ int   cj[160];
    int pos = blockIdx.x, i = pos & (NPTS-1);
    int tid = threadIdx.x, warp = tid >> 5, lane = tid & 31;
    const float* row = g_dist + (size_t)pos*NPTS;
    int base = warp*256;
    float v[8];
    #pragma unroll
    for (int s = 0; s < 8; s++) { int j = base+lane+32*s; float x = row[j]; v[s] = (j==i)?1e30f:x; }
    for (int kk = 0; kk < KNN; kk++) {
        float bv = v[0]; int bs = 0;
        #pragma unroll
        for (int s = 1; s < 8; s++) if (v[s] < bv) { bv = v[s]; bs = s; }
        int bj = base + lane + 32*bs;
        #pragma unroll
        for (int off = 16; off > 0; off >>= 1) {
            float ov = __shfl_down_sync(0xffffffffu, bv, off);
            int   oj = __shfl_down_sync(0xffffffffu, bj, off);
            if (ov < bv || (ov == bv && oj < bj)) { bv = ov; bj = oj; }
        }
        bv = __shfl_sync(0xffffffffu, bv, 0);
        bj = __shfl_sync(0xffffffffu, bj, 0);
        #pragma unroll
        for (int s = 0; s < 8; s++) if (base + lane + 32*s == bj) v[s] = 1e30f;
        if (lane == 0) { cv[warp*KNN+kk] = bv; cj[warp*KNN+kk] = bj; }
    }
    __syncthreads();
    if (warp == 0) {
        float mv[5]; int mj[5];
        #pragma unroll
        for (int s = 0; s < 5; s++) { int c = lane+32*s; mv[s] = cv[c]; mj[s] = cj[c]; }
        for (int kk = 0; kk < KNN; kk++) {
            float bv = mv[0]; int bj = mj[0];
            #pragma unroll
            for (int s = 1; s < 5; s++) if (mv[s] < bv || (mv[s] == bv && mj[s] < bj)) { bv = mv[s]; bj = mj[s]; }
            #pragma unroll
            for (int off = 16; off > 0; off >>= 1) {
                float ov = __shfl_down_sync(0xffffffffu, bv, off);
                int   oj = __shfl_down_sync(0xffffffffu, bj, off);
                if (ov < bv || (ov == bv && oj < bj)) { bv = ov; bj = oj; }
            }
            bv = __shfl_sync(0xffffffffu, bv, 0);
            bj = __shfl_sync(0xffffffffu, bj, 0);
            #pragma unroll
            for (int s = 0; s < 5; s++) if (mj[s] == bj) mv[s] = 1e30f;
            if (lane == 0) g_idx[pos*KNN + kk] = bj;
        }
    }
}

// ---------------- conv1: 2-pass fp16 HMMA GEMM -------------------------------
// smem: NB 0(40960) CT 40960(2048) B0 43008(32768) B1 75776(32768)
//       BI 108544(1024) ID 109568(1280) SZ 110848
#define C1_CT  40960
#define C1_B0  43008
#define C1_B1  75776
#define C1_BI  108544
#define C1_ID  109568
#define C1_SZ  110848

__global__ __launch_bounds__(640, 1) void k_conv1m(const float* __restrict__ b1) {
    extern __shared__ char sm[];
    uint32_t su = s2u(sm);
    int tid = threadIdx.x, wid = tid >> 5, lane = tid & 31;
    int pos0 = blockIdx.x*16, b = pos0 >> 11;
    int* s_id = (int*)(sm + C1_ID);
    float* s_bi = (float*)(sm + C1_BI);

    if (tid < 320) s_id[tid] = g_idx[pos0*KNN + tid];
    if (tid < 256) s_bi[tid] = b1[tid];
    __syncthreads();

    auto loadB = [&](int cc, int sel, uint32_t bufoff) {
        const char* wbase = (const char*)g_w1s + (size_t)sel*(12*256*64)*2;
        for (int e = tid; e < 2048; e += 640) {
            int co = e >> 3, u = e & 7;
            const char* src = wbase + (size_t)(cc*256 + co)*128 + u*16;
            uint32_t dst = su + bufoff + co*128 + ((u ^ (co & 7)) << 4);
            CP16(dst, src);
        }
    };
    loadB(0, 0, C1_B0); CP_COMMIT();
    loadB(0, 1, C1_B1); CP_COMMIT();

    // stage nb / ct tables (swizzled, fp16 single)
    const uint4* xh4 = (const uint4*)g_xh;
    for (int e = tid; e < 2560; e += 640) {
        int row = e >> 3, u = e & 7;
        int gp = (b << 11) + s_id[row];
        int sw = (u ^ (row & 7)) << 4;
        *(uint4*)(sm + row*128 + sw) = xh4[gp*8 + u];
    }
    if (tid < 128) {
        int row = tid >> 3, u = tid & 7;
        int sw = (u ^ (row & 7)) << 4;
        *(uint4*)(sm + C1_CT + row*128 + sw) = xh4[(pos0+row)*8 + u];
    }

    int mh = wid >> 2, nq = wid & 3;        // 5 x 4
    int rr = (lane & 7) + ((lane >> 3) & 1)*8;
    int kx = lane >> 4;
    int Ra0 = mh*32 + rr, Ra1 = Ra0 + 16;
    int p0 = Ra0/10, jb0 = p0*20 + (Ra0 - p0*10);
    int p1 = Ra1/10, jb1 = p1*20 + (Ra1 - p1*10);
    int bn = lane & 7, bg = lane >> 3;      // B x4 lane decomp

    float acc[2][8][4];
    #pragma unroll
    for (int mt = 0; mt < 2; mt++)
        #pragma unroll
        for (int nt = 0; nt < 8; nt++)
            #pragma unroll
            for (int q = 0; q < 4; q++) acc[mt][nt][q] = 0.f;

    auto combo = [&](uint32_t atab, uint32_t bbase, int ar0, int ar1) {
        #pragma unroll
        for (int ks = 0; ks < 4; ks++) {
            uint32_t a0[4], a1[4];
            uint32_t ad0 = atab + ar0*128 + ((((ks<<1)|kx) ^ (ar0 & 7)) << 4);
            uint32_t ad1 = atab + ar1*128 + ((((ks<<1)|kx) ^ (ar1 & 7)) << 4);
            LDSM4(a0[0],a0[1],a0[2],a0[3], ad0);
            LDSM4(a1[0],a1[1],a1[2],a1[3], ad1);
            #pragma unroll
            for (int ng = 0; ng < 4; ng++) {
                int na = nq*64 + ng*16 + ((bg >> 1) << 3) + bn;
                int seg = (ks << 1) | (bg & 1);
                uint32_t bd = bbase + na*128 + ((seg ^ (na & 7)) << 4);
                uint32_t r0, r1, r2, r3;
                LDSM4(r0, r1, r2, r3, bd);
                mma16816(acc[0][2*ng],   a0, r0, r1);
                mma16816(acc[1][2*ng],   a1, r0, r1);
                mma16816(acc[0][2*ng+1], a0, r2, r3);
                mma16816(acc[1][2*ng+1], a1, r2, r3);
            }
        }
    };

    for (int cc = 0; cc < 12; cc++) {
        int ar0, ar1; uint32_t tab;
        if (cc < 11) { ar0 = jb0 + cc; ar1 = jb1 + cc; tab = su; }
        else         { ar0 = p0;       ar1 = p1;       tab = su + C1_CT; }
        CP_WAIT1(); __syncthreads();
        combo(tab, su + C1_B0, ar0, ar1);
        __syncthreads();
        if (cc < 11) { loadB(cc+1, 0, C1_B0); CP_COMMIT(); }
        CP_WAIT1(); __syncthreads();
        combo(tab, su + C1_B1, ar0, ar1);
        __syncthreads();
        if (cc < 11) { loadB(cc+1, 1, C1_B1); CP_COMMIT(); }
    }

    #pragma unroll
    for (int mt = 0; mt < 2; mt++) {
        int Ra = mh*32 + mt*16 + (lane >> 2);
        int Rb = Ra + 8;
        int pa = Ra/10, ja = Ra - pa*10;
        int pb = Rb/10, jb = Rb - pb*10;
        #pragma unroll
        for (int nt = 0; nt < 8; nt++) {
            int co = nq*64 + nt*8 + (lane & 3)*2;
            float b0 = s_bi[co], b1v = s_bi[co+1];
            float2 v0; v0.x = acc[mt][nt][0] + b0; v0.y = acc[mt][nt][1] + b1v;
            *(float2*)&g_h[(size_t)(pos0+pa)*2560 + ja*256 + co] = v0;
            float2 v1; v1.x = acc[mt][nt][2] + b0; v1.y = acc[mt][nt][3] + b1v;
            *(float2*)&g_h[(size_t)(pos0+pb)*2560 + jb*256 + co] = v1;
        }
    }
}

// ---------------- BN stats + finalize ----------------------------------------
__global__ __launch_bounds__(256) void k_stats1() {
    int tid = threadIdx.x;
    size_t base = (size_t)blockIdx.x*128*2560;
    float s = 0.f, ss = 0.f;
    for (int i = 0; i < 1280; i++) {
        float v = g_h[base + (size_t)i*256 + tid];
        s += v; ss += v*v;
    }
    atomicAdd(&g_s1[tid], s);
    atomicAdd(&g_ss1[tid], ss);
}
__global__ __launch_bounds__(256) void k_stats2() {
    int tid = threadIdx.x;
    size_t base = (size_t)blockIdx.x*128*256;
    float s = 0.f, ss = 0.f;
    for (int i = 0; i < 128; i++) {
        float v = g_out2[base + i*256 + tid];
        s += v; ss += v*v;
    }
    atomicAdd(&g_s2[tid], s);
    atomicAdd(&g_ss2[tid], ss);
}
__global__ void k_bnfin(const float* __restrict__ gam, const float* __restrict__ bet, int which) {
    int i = threadIdx.x;
    float s, ss, invcnt;
    if (which == 0) { s = g_s1[i]; ss = g_ss1[i]; invcnt = 1.f/163840.f; }
    else            { s = g_s2[i]; ss = g_ss2[i]; invcnt = 1.f/16384.f; }
    float mean = s*invcnt;
    float var  = ss*invcnt - mean*mean;
    float a = gam[i]*rsqrtf(var + BN_EPS);
    float c = bet[i] - mean*a;
    if (which == 0) { g_a1[i] = a; g_c1[i] = c; }
    else            { g_a2[i] = a; g_c2[i] = c; }
}

// ---------------- conv2: 2-pass fp16 HMMA GEMM -------------------------------
// smem: AH 0(8192) B0 8192(32768) B1 40960(32768) ID 73728(5120)
//       A1 78848 C1 79872 BI 80896 SZ 81920
#define C2_B0 8192
#define C2_B1 40960
#define C2_ID 73728
#define C2_A1 78848
#define C2_C1 79872
#define C2_BI 80896
#define C2_SZ 81920

__global__ __launch_bounds__(256, 2) void k_conv2m(const float* __restrict__ b2) {
    extern __shared__ char sm[];
    uint32_t su = s2u(sm);
    int tid = threadIdx.x, wid = tid >> 5, lane = tid & 31;
    int pos0 = blockIdx.x*64, b = pos0 >> 11;
    int* s_id = (int*)(sm + C2_ID);
    float* s_a1 = (float*)(sm + C2_A1);
    float* s_c1 = (float*)(sm + C2_C1);
    float* s_bi = (float*)(sm + C2_BI);

    for (int e = tid; e < 1280; e += 256) s_id[e] = g_idx[pos0*KNN + e];
    s_a1[tid] = g_a1[tid]; s_c1[tid] = g_c1[tid]; s_bi[tid] = b2[tid];
    __syncthreads();

    auto loadB = [&](int kc, int sel, uint32_t bufoff) {
        const char* wbase = (const char*)g_w2s + (size_t)sel*((size_t)61*256*64)*2;
        for (int e = tid; e < 2048; e += 256) {
            int co = e >> 3, u = e & 7;
            const char* src = wbase + (size_t)(kc*256 + co)*128 + u*16;
            uint32_t dst = su + bufoff + co*128 + ((u ^ (co & 7)) << 4);
            CP16(dst, src);
        }
    };
    loadB(0, 0, C2_B0); CP_COMMIT();
    loadB(0, 1, C2_B1); CP_COMMIT();

    int mh = wid >> 2, nq = wid & 3;          // 2 x 4
    int rr = (lane & 7) + ((lane >> 3) & 1)*8;
    int kx = lane >> 4;
    int Ra0 = mh*32 + rr, Ra1 = Ra0 + 16;
    int bn = lane & 7, bg = lane >> 3;

    float acc[2][8][4];
    #pragma unroll
    for (int mt = 0; mt < 2; mt++)
        #pragma unroll
        for (int nt = 0; nt < 8; nt++)
            #pragma unroll
            for (int q = 0; q < 4; q++) acc[mt][nt][q] = 0.f;

    auto combo = [&](uint32_t atab, uint32_t bbase) {
        #pragma unroll
        for (int ks = 0; ks < 4; ks++) {
            uint32_t a0[4], a1[4];
            uint32_t ad0 = atab + Ra0*128 + ((((ks<<1)|kx) ^ (Ra0 & 7)) << 4);
            uint32_t ad1 = atab + Ra1*128 + ((((ks<<1)|kx) ^ (Ra1 & 7)) << 4);
            LDSM4(a0[0],a0[1],a0[2],a0[3], ad0);
            LDSM4(a1[0],a1[1],a1[2],a1[3], ad1);
            #pragma unroll
            for (int ng = 0; ng < 4; ng++) {
                int na = nq*64 + ng*16 + ((bg >> 1) << 3) + bn;
                int seg = (ks << 1) | (bg & 1);
                uint32_t bd = bbase + na*128 + ((seg ^ (na & 7)) << 4);
                uint32_t r0, r1, r2, r3;
                LDSM4(r0, r1, r2, r3, bd);
                mma16816(acc[0][2*ng],   a0, r0, r1);
                mma16816(acc[1][2*ng],   a1, r0, r1);
                mma16816(acc[0][2*ng+1], a0, r2, r3);
                mma16816(acc[1][2*ng+1], a1, r2, r3);
            }
        }
    };

    for (int kc = 0; kc < 61; kc++) {
        // build A chunk (single fp16), swizzled
        for (int e = tid; e < 4096; e += 256) {
            int pp = e >> 6, kk = e & 63;
            int k = kc*64 + kk;
            unsigned short hv16;
            if (k < 64) {
                hv16 = g_xh[(pos0+pp)*64 + k];
            } else if (k < 1344) {
                int u = k - 64; int t = u >> 6, c = u & 63;
                int gp = (b << 11) + s_id[pp*KNN + t];
                hv16 = g_xh[gp*64 + c];
            } else {
                int u = k - 1344;
                int ch = u & 255;
                float hv = g_h[(size_t)(pos0+pp)*2560 + u];
                float x = fmaf(s_a1[ch], hv, s_c1[ch]);
                float v = x > 0.f ? x : 0.01f*x;
                hv16 = fhb(v);
            }
            int off = pp*128 + (((kk >> 3) ^ (pp & 7)) << 4) + (kk & 7)*2;
            *(unsigned short*)(sm + off) = hv16;
        }
        CP_WAIT1(); __syncthreads();
        combo(su, su + C2_B0);
        __syncthreads();
        if (kc < 60) { loadB(kc+1, 0, C2_B0); CP_COMMIT(); }
        CP_WAIT1(); __syncthreads();
        combo(su, su + C2_B1);
        __syncthreads();
        if (kc < 60) { loadB(kc+1, 1, C2_B1); CP_COMMIT(); }
    }

    #pragma unroll
    for (int mt = 0; mt < 2; mt++) {
        int Ra = mh*32 + mt*16 + (lane >> 2);
        int Rb = Ra + 8;
        #pragma unroll
        for (int nt = 0; nt < 8; nt++) {
            int co = nq*64 + nt*8 + (lane & 3)*2;
            float b0 = s_bi[co], b1v = s_bi[co+1];
            float2 v0; v0.x = acc[mt][nt][0] + b0; v0.y = acc[mt][nt][1] + b1v;
            *(float2*)&g_out2[(size_t)(pos0+Ra)*256 + co] = v0;
            float2 v1; v1.x = acc[mt][nt][2] + b0; v1.y = acc[mt][nt][3] + b1v;
            *(float2*)&g_out2[(size_t)(pos0+Rb)*256 + co] = v1;
        }
    }
}

// ---------------- BN2 + relu + final reshape ---------------------------------
__global__ __launch_bounds__(256) void k_final(float* __restrict__ out) {
    __shared__ float s_t[32][257];
    __shared__ float sa[CO2], sc[CO2];
    int bx = blockIdx.x;
    int b = bx >> 6, n0 = (bx & 63)*32;
    int tid = threadIdx.x;
    sa[tid] = g_a2[tid]; sc[tid] = g_c2[tid];
    for (int e = tid; e < 32*256; e += 256) {
        int nn = e >> 8, co = e & 255;
        s_t[nn][co] = g_out2[(size_t)((b << 11) + n0 + nn)*256 + co];
    }
    __syncthreads();
    for (int e = tid; e < 32*256; e += 256) {
        int co = e >> 5, nn = e & 31;
        float v = fmaf(sa[co], s_t[nn][co], sc[co]);
        out[(size_t)b*(128*4096) + (co >> 1)*4096 + ((co & 1) << 11) + n0 + nn] = fmaxf(v, 0.f);
    }
}

// ---------------- launch -----------------------------------------------------
extern "C" void kernel_launch(void* const* d_in, const int* in_sizes, int n_in,
                              void* d_out, int out_size) {
    const float* x   = (const float*)d_in[0];
    const float* w1  = (const float*)d_in[1];
    const float* b1  = (const float*)d_in[2];
    const float* g1  = (const float*)d_in[3];
    const float* be1 = (const float*)d_in[4];
    const float* w2  = (const float*)d_in[5];
    const float* b2  = (const float*)d_in[6];
    const float* g2  = (const float*)d_in[7];
    const float* be2 = (const float*)d_in[8];
    float* out = (float*)d_out;

    cudaFuncSetAttribute(k_conv1m, cudaFuncAttributeMaxDynamicSharedMemorySize, C1_SZ);
    cudaFuncSetAttribute(k_conv2m, cudaFuncAttributeMaxDynamicSharedMemorySize, C2_SZ);

    k_zero<<<1, 256>>>();
    k_xt<<<NPOS, 64>>>(x);
    k_w1m<<<12*16384/256, 256>>>(w1);
    k_w2m<<<61*16384/256, 256>>>(w2);
    k_dist<<<dim3(NPTS/64, NPTS/64, BB), 256>>>();
    k_knn<<<NPOS, 256>>>();
    k_conv1m<<<NPOS/16, 640, C1_SZ>>>(b1);
    k_stats1<<<128, 256>>>();
    k_bnfin<<<1, 256>>>(g1, be1, 0);
    k_conv2m<<<NPOS/64, 256, C2_SZ>>>(b2);
    k_stats2<<<128, 256>>>();
    k_bnfin<<<1, 256>>>(g2, be2, 1);
    k_final<<<BB*64, 256>>>(out);
}

// round 14
// speedup vs baseline: 10.0788x; 1.1700x over previous
#include <cuda_runtime.h>
#include <cuda_fp16.h>
#include <math.h>
#include <cstdint>

#define BB   8
#define FIN  64
#define NPTS 2048
#define KNN  20
#define RTAP 11
#define CO1  256
#define CO2  256
#define NPOS  (BB*NPTS)
#define BN_EPS 1e-5f

// ---------------- scratch ----------------------------------------------------
__device__ float g_xt[NPOS*FIN];
__device__ float g_sq[NPOS];
__device__ float g_dist[(size_t)NPOS*NPTS];
__device__ int   g_idx[NPOS*KNN];
__device__ __align__(16) unsigned short g_xh[NPOS*FIN];            // fp16(x)
__device__ __align__(16) unsigned short g_w1s[12*256*64];          // [cc][co][c] fp16
__device__ __align__(16) unsigned short g_w2s[(size_t)61*256*64];  // [kc][co][c] fp16
__device__ float g_h[(size_t)NPOS*2560];        // [pos][j][co]  j<10
__device__ float g_out2[(size_t)NPOS*CO2];      // [pos][co]
__device__ float g_s1[CO1], g_ss1[CO1], g_s2[CO2], g_ss2[CO2];
__device__ float g_a1[CO1], g_c1[CO1], g_a2[CO2], g_c2[CO2];

__device__ __forceinline__ unsigned short fhb(float x) {
    __half h = __float2half_rn(x); return *reinterpret_cast<unsigned short*>(&h);
}

__device__ __forceinline__ uint32_t s2u(const void* p) {
    uint32_t a; asm("{ .reg .u64 t; cvta.to.shared.u64 t, %1; cvt.u32.u64 %0, t; }" : "=r"(a) : "l"(p)); return a;
}
__device__ __forceinline__ void mma16816(float* c, const uint32_t* a, uint32_t b0, uint32_t b1) {
    asm volatile("mma.sync.aligned.m16n8k16.row.col.f32.f16.f16.f32 "
        "{%0,%1,%2,%3}, {%4,%5,%6,%7}, {%8,%9}, {%0,%1,%2,%3};"
        : "+f"(c[0]), "+f"(c[1]), "+f"(c[2]), "+f"(c[3])
        : "r"(a[0]), "r"(a[1]), "r"(a[2]), "r"(a[3]), "r"(b0), "r"(b1));
}
#define LDSM4(r0,r1,r2,r3,addr) \
    asm volatile("ldmatrix.sync.aligned.m8n8.x4.shared.b16 {%0,%1,%2,%3}, [%4];" \
        : "=r"(r0),"=r"(r1),"=r"(r2),"=r"(r3) : "r"(addr))
#define CP16(dst, src) asm volatile("cp.async.cg.shared.global [%0], [%1], 16;" :: "r"(dst), "l"(src))
#define CP_COMMIT()    asm volatile("cp.async.commit_group;" ::: "memory")
#define CP_WAIT1()     asm volatile("cp.async.wait_group 1;" ::: "memory")
#define CP_WAIT0()     asm volatile("cp.async.wait_group 0;" ::: "memory")

// ---------------- prep -------------------------------------------------------
__global__ void k_zero() {
    int t = threadIdx.x;
    g_s1[t]=0.f; g_ss1[t]=0.f; g_s2[t]=0.f; g_ss2[t]=0.f;
}

__global__ void k_xt(const float* __restrict__ x) {
    int pos = blockIdx.x;
    int b = pos >> 11, n = pos & (NPTS-1);
    int d = threadIdx.x;
    float v = x[((size_t)(b*FIN + d))*NPTS + n];
    g_xt[pos*FIN + d] = v;
    g_xh[pos*FIN + d] = fhb(v);
    __shared__ float red[FIN];
    red[d] = v*v;
    __syncthreads();
    #pragma unroll
    for (int s = 32; s > 0; s >>= 1) { if (d < s) red[d] += red[d+s]; __syncthreads(); }
    if (d == 0) g_sq[pos] = red[0];
}

__global__ void k_w1m(const float* __restrict__ w1) {
    int e = blockIdx.x*256 + threadIdx.x;   // 12*16384
    int cc = e >> 14, rem = e & 16383;
    int co = rem >> 6, c = rem & 63;
    float W;
    if (cc < 11) W = w1[co*1408 + (64+c)*RTAP + cc];
    else {
        W = 0.f;
        for (int r = 0; r < RTAP; r++) W += w1[co*1408 + c*RTAP + r] - w1[co*1408 + (64+c)*RTAP + r];
    }
    g_w1s[(size_t)(cc*256 + co)*64 + c] = fhb(W);
}

__global__ void k_w2m(const float* __restrict__ w2) {
    int e = blockIdx.x*256 + threadIdx.x;   // 61*16384
    int kc = e >> 14, rem = e & 16383;
    int co = rem >> 6, c = rem & 63;
    int k = kc*64 + c;
    float W;
    if (k < 64) {
        W = 0.f;
        for (int t = 0; t < KNN; t++) W += w2[co*5120 + k*40 + t] - w2[co*5120 + (64+k)*40 + t];
    } else if (k < 1344) {
        int u = k - 64; int t = u >> 6, cx = u & 63;
        W = w2[co*5120 + (64+cx)*40 + t];
    } else {
        int u = k - 1344; int j = u >> 8, ch = u & 255;
        W = w2[co*5120 + (ch >> 1)*40 + 20 + (ch & 1)*10 + j];
    }
    g_w2s[(size_t)(kc*256 + co)*64 + c] = fhb(W);
}

// ---------------- pairwise distances: 64x64 tile, 4x4/thread -----------------
__global__ __launch_bounds__(256) void k_dist() {
    __shared__ float sa[64][68], sb[64][68];   // d-major
    int b = blockIdx.z, i0 = blockIdx.y*64, j0 = blockIdx.x*64;
    int tid = threadIdx.x;
    int tx = tid & 15, ty = tid >> 4;
    const float4* xt4 = (const float4*)g_xt;
    for (int e = tid; e < 1024; e += 256) {
        int r = e >> 4, u = e & 15;
        float4 va = xt4[((size_t)(b*NPTS) + i0 + r)*16 + u];
        sa[u*4+0][r] = va.x; sa[u*4+1][r] = va.y; sa[u*4+2][r] = va.z; sa[u*4+3][r] = va.w;
        float4 vb = xt4[((size_t)(b*NPTS) + j0 + r)*16 + u];
        sb[u*4+0][r] = vb.x; sb[u*4+1][r] = vb.y; sb[u*4+2][r] = vb.z; sb[u*4+3][r] = vb.w;
    }
    __syncthreads();
    float acc[4][4];
    #pragma unroll
    for (int i = 0; i < 4; i++)
        #pragma unroll
        for (int j = 0; j < 4; j++) acc[i][j] = 0.f;
    #pragma unroll 4
    for (int d = 0; d < 64; d++) {
        float4 av = *(const float4*)&sa[d][ty*4];
        float4 bv = *(const float4*)&sb[d][tx*4];
        float a[4] = {av.x, av.y, av.z, av.w};
        float bq[4] = {bv.x, bv.y, bv.z, bv.w};
        #pragma unroll
        for (int i = 0; i < 4; i++)
            #pragma unroll
            for (int j = 0; j < 4; j++) acc[i][j] = fmaf(a[i], bq[j], acc[i][j]);
    }
    float sqj[4];
    #pragma unroll
    for (int j = 0; j < 4; j++) sqj[j] = g_sq[b*NPTS + j0 + tx*4 + j];
    #pragma unroll
    for (int i = 0; i < 4; i++) {
        float sqi = g_sq[b*NPTS + i0 + ty*4 + i];
        float4 o;
        o.x = sqi + sqj[0] - 2.f*acc[i][0];
        o.y = sqi + sqj[1] - 2.f*acc[i][1];
        o.z = sqi + sqj[2] - 2.f*acc[i][2];
        o.w = sqi + sqj[3] - 2.f*acc[i][3];
        *(float4*)&g_dist[((size_t)(b*NPTS) + i0 + ty*4 + i)*NPTS + j0 + tx*4] = o;
    }
}

// ---------------- top-20 (unchanged) -----------------------------------------
__global__ __launch_bounds__(256) void k_knn() {
    __shared__ float cv[160];
    __shared__ int   cj[160];
    int pos = blockIdx.x, i = pos & (NPTS-1);
    int tid = threadIdx.x, warp = tid >> 5, lane = tid & 31;
    const float* row = g_dist + (size_t)pos*NPTS;
    int base = warp*256;
    float v[8];
    #pragma unroll
    for (int s = 0; s < 8; s++) { int j = base+lane+32*s; float x = row[j]; v[s] = (j==i)?1e30f:x; }
    for (int kk = 0; kk < KNN; kk++) {
        float bv = v[0]; int bs = 0;
        #pragma unroll
        for (int s = 1; s < 8; s++) if (v[s] < bv) { bv = v[s]; bs = s; }
        int bj = base + lane + 32*bs;
        #pragma unroll
        for (int off = 16; off > 0; off >>= 1) {
            float ov = __shfl_down_sync(0xffffffffu, bv, off);
            int   oj = __shfl_down_sync(0xffffffffu, bj, off);
            if (ov < bv || (ov == bv && oj < bj)) { bv = ov; bj = oj; }
        }
        bv = __shfl_sync(0xffffffffu, bv, 0);
        bj = __shfl_sync(0xffffffffu, bj, 0);
        #pragma unroll
        for (int s = 0; s < 8; s++) if (base + lane + 32*s == bj) v[s] = 1e30f;
        if (lane == 0) { cv[warp*KNN+kk] = bv; cj[warp*KNN+kk] = bj; }
    }
    __syncthreads();
    if (warp == 0) {
        float mv[5]; int mj[5];
        #pragma unroll
        for (int s = 0; s < 5; s++) { int c = lane+32*s; mv[s] = cv[c]; mj[s] = cj[c]; }
        for (int kk = 0; kk < KNN; kk++) {
            float bv = mv[0]; int bj = mj[0];
            #pragma unroll
            for (int s = 1; s < 5; s++) if (mv[s] < bv || (mv[s] == bv && mj[s] < bj)) { bv = mv[s]; bj = mj[s]; }
            #pragma unroll
            for (int off = 16; off > 0; off >>= 1) {
                float ov = __shfl_down_sync(0xffffffffu, bv, off);
                int   oj = __shfl_down_sync(0xffffffffu, bj, off);
                if (ov < bv || (ov == bv && oj < bj)) { bv = ov; bj = oj; }
            }
            bv = __shfl_sync(0xffffffffu, bv, 0);
            bj = __shfl_sync(0xffffffffu, bj, 0);
            #pragma unroll
            for (int s = 0; s < 5; s++) if (mj[s] == bj) mv[s] = 1e30f;
            if (lane == 0) g_idx[pos*KNN + kk] = bj;
        }
    }
}

// ---------------- conv1: single-pass fp16 HMMA GEMM --------------------------
// smem: NB 0(40960) CT 40960(2048) B0 43008(32768) B1 75776(32768)
//       BI 108544(1024) ID 109568(1280) SZ 110848
#define C1_CT  40960
#define C1_B0  43008
#define C1_B1  75776
#define C1_BI  108544
#define C1_ID  109568
#define C1_SZ  110848

__global__ __launch_bounds__(640, 1) void k_conv1m(const float* __restrict__ b1) {
    extern __shared__ char sm[];
    uint32_t su = s2u(sm);
    int tid = threadIdx.x, wid = tid >> 5, lane = tid & 31;
    int pos0 = blockIdx.x*16, b = pos0 >> 11;
    int* s_id = (int*)(sm + C1_ID);
    float* s_bi = (float*)(sm + C1_BI);

    if (tid < 320) s_id[tid] = g_idx[pos0*KNN + tid];
    if (tid < 256) s_bi[tid] = b1[tid];
    __syncthreads();

    auto loadB = [&](int cc, uint32_t bufoff) {
        for (int e = tid; e < 2048; e += 640) {
            int co = e >> 3, u = e & 7;
            const char* src = (const char*)g_w1s + (size_t)(cc*256 + co)*128 + u*16;
            uint32_t dst = su + bufoff + co*128 + ((u ^ (co & 7)) << 4);
            CP16(dst, src);
        }
    };
    loadB(0, C1_B0); CP_COMMIT();

    // stage nb / ct tables (swizzled, fp16)
    const uint4* xh4 = (const uint4*)g_xh;
    for (int e = tid; e < 2560; e += 640) {
        int row = e >> 3, u = e & 7;
        int gp = (b << 11) + s_id[row];
        int sw = (u ^ (row & 7)) << 4;
        *(uint4*)(sm + row*128 + sw) = xh4[gp*8 + u];
    }
    if (tid < 128) {
        int row = tid >> 3, u = tid & 7;
        int sw = (u ^ (row & 7)) << 4;
        *(uint4*)(sm + C1_CT + row*128 + sw) = xh4[(pos0+row)*8 + u];
    }

    int mh = wid >> 2, nq = wid & 3;        // 5 x 4
    int rr = (lane & 7) + ((lane >> 3) & 1)*8;
    int kx = lane >> 4;
    int Ra0 = mh*32 + rr, Ra1 = Ra0 + 16;
    int p0 = Ra0/10, jb0 = p0*20 + (Ra0 - p0*10);
    int p1 = Ra1/10, jb1 = p1*20 + (Ra1 - p1*10);
    int bn = lane & 7, bg = lane >> 3;      // B x4 lane decomp

    float acc[2][8][4];
    #pragma unroll
    for (int mt = 0; mt < 2; mt++)
        #pragma unroll
        for (int nt = 0; nt < 8; nt++)
            #pragma unroll
            for (int q = 0; q < 4; q++) acc[mt][nt][q] = 0.f;

    auto combo = [&](uint32_t atab, uint32_t bbase, int ar0, int ar1) {
        #pragma unroll
        for (int ks = 0; ks < 4; ks++) {
            uint32_t a0[4], a1[4];
            uint32_t ad0 = atab + ar0*128 + ((((ks<<1)|kx) ^ (ar0 & 7)) << 4);
            uint32_t ad1 = atab + ar1*128 + ((((ks<<1)|kx) ^ (ar1 & 7)) << 4);
            LDSM4(a0[0],a0[1],a0[2],a0[3], ad0);
            LDSM4(a1[0],a1[1],a1[2],a1[3], ad1);
            #pragma unroll
            for (int ng = 0; ng < 4; ng++) {
                int na = nq*64 + ng*16 + ((bg >> 1) << 3) + bn;
                int seg = (ks << 1) | (bg & 1);
                uint32_t bd = bbase + na*128 + ((seg ^ (na & 7)) << 4);
                uint32_t r0, r1, r2, r3;
                LDSM4(r0, r1, r2, r3, bd);
                mma16816(acc[0][2*ng],   a0, r0, r1);
                mma16816(acc[1][2*ng],   a1, r0, r1);
                mma16816(acc[0][2*ng+1], a0, r2, r3);
                mma16816(acc[1][2*ng+1], a1, r2, r3);
            }
        }
    };

    for (int cc = 0; cc < 12; cc++) {
        int ar0, ar1; uint32_t tab;
        if (cc < 11) { ar0 = jb0 + cc; ar1 = jb1 + cc; tab = su; }
        else         { ar0 = p0;       ar1 = p1;       tab = su + C1_CT; }
        uint32_t curbuf = (cc & 1) ? C1_B1 : C1_B0;
        if (cc + 1 < 12) {
            loadB(cc + 1, ((cc + 1) & 1) ? C1_B1 : C1_B0); CP_COMMIT();
            CP_WAIT1();
        } else {
            CP_WAIT0();
        }
        __syncthreads();
        combo(tab, su + curbuf, ar0, ar1);
        __syncthreads();
    }

    #pragma unroll
    for (int mt = 0; mt < 2; mt++) {
        int Ra = mh*32 + mt*16 + (lane >> 2);
        int Rb = Ra + 8;
        int pa = Ra/10, ja = Ra - pa*10;
        int pb = Rb/10, jb = Rb - pb*10;
        #pragma unroll
        for (int nt = 0; nt < 8; nt++) {
            int co = nq*64 + nt*8 + (lane & 3)*2;
            float b0 = s_bi[co], b1v = s_bi[co+1];
            float2 v0; v0.x = acc[mt][nt][0] + b0; v0.y = acc[mt][nt][1] + b1v;
            *(float2*)&g_h[(size_t)(pos0+pa)*2560 + ja*256 + co] = v0;
            float2 v1; v1.x = acc[mt][nt][2] + b0; v1.y = acc[mt][nt][3] + b1v;
            *(float2*)&g_h[(size_t)(pos0+pb)*2560 + jb*256 + co] = v1;
        }
    }
}

// ---------------- BN stats + finalize ----------------------------------------
__global__ __launch_bounds__(256) void k_stats1() {
    int tid = threadIdx.x;
    size_t base = (size_t)blockIdx.x*128*2560;
    float s = 0.f, ss = 0.f;
    for (int i = 0; i < 1280; i++) {
        float v = g_h[base + (size_t)i*256 + tid];
        s += v; ss += v*v;
    }
    atomicAdd(&g_s1[tid], s);
    atomicAdd(&g_ss1[tid], ss);
}
__global__ __launch_bounds__(256) void k_stats2() {
    int tid = threadIdx.x;
    size_t base = (size_t)blockIdx.x*128*256;
    float s = 0.f, ss = 0.f;
    for (int i = 0; i < 128; i++) {
        float v = g_out2[base + i*256 + tid];
        s += v; ss += v*v;
    }
    atomicAdd(&g_s2[tid], s);
    atomicAdd(&g_ss2[tid], ss);
}
__global__ void k_bnfin(const float* __restrict__ gam, const float* __restrict__ bet, int which) {
    int i = threadIdx.x;
    float s, ss, invcnt;
    if (which == 0) { s = g_s1[i]; ss = g_ss1[i]; invcnt = 1.f/163840.f; }
    else            { s = g_s2[i]; ss = g_ss2[i]; invcnt = 1.f/16384.f; }
    float mean = s*invcnt;
    float var  = ss*invcnt - mean*mean;
    float a = gam[i]*rsqrtf(var + BN_EPS);
    float c = bet[i] - mean*a;
    if (which == 0) { g_a1[i] = a; g_c1[i] = c; }
    else            { g_a2[i] = a; g_c2[i] = c; }
}

// ---------------- conv2: single-pass fp16 HMMA GEMM --------------------------
// smem: AH 0(8192) B0 8192(32768) B1 40960(32768) ID 73728(5120)
//       A1 78848 C1 79872 BI 80896 SZ 81920
#define C2_B0 8192
#define C2_B1 40960
#define C2_ID 73728
#define C2_A1 78848
#define C2_C1 79872
#define C2_BI 80896
#define C2_SZ 81920

__global__ __launch_bounds__(256, 2) void k_conv2m(const float* __restrict__ b2) {
    extern __shared__ char sm[];
    uint32_t su = s2u(sm);
    int tid = threadIdx.x, wid = tid >> 5, lane = tid & 31;
    int pos0 = blockIdx.x*64, b = pos0 >> 11;
    int* s_id = (int*)(sm + C2_ID);
    float* s_a1 = (float*)(sm + C2_A1);
    float* s_c1 = (float*)(sm + C2_C1);
    float* s_bi = (float*)(sm + C2_BI);

    for (int e = tid; e < 1280; e += 256) s_id[e] = g_idx[pos0*KNN + e];
    s_a1[tid] = g_a1[tid]; s_c1[tid] = g_c1[tid]; s_bi[tid] = b2[tid];
    __syncthreads();

    auto loadB = [&](int kc, uint32_t bufoff) {
        for (int e = tid; e < 2048; e += 256) {
            int co = e >> 3, u = e & 7;
            const char* src = (const char*)g_w2s + (size_t)(kc*256 + co)*128 + u*16;
            uint32_t dst = su + bufoff + co*128 + ((u ^ (co & 7)) << 4);
            CP16(dst, src);
        }
    };
    loadB(0, C2_B0); CP_COMMIT();

    int mh = wid >> 2, nq = wid & 3;          // 2 x 4
    int rr = (lane & 7) + ((lane >> 3) & 1)*8;
    int kx = lane >> 4;
    int Ra0 = mh*32 + rr, Ra1 = Ra0 + 16;
    int bn = lane & 7, bg = lane >> 3;

    float acc[2][8][4];
    #pragma unroll
    for (int mt = 0; mt < 2; mt++)
        #pragma unroll
        for (int nt = 0; nt < 8; nt++)
            #pragma unroll
            for (int q = 0; q < 4; q++) acc[mt][nt][q] = 0.f;

    auto combo = [&](uint32_t bbase) {
        #pragma unroll
        for (int ks = 0; ks < 4; ks++) {
            uint32_t a0[4], a1[4];
            uint32_t ad0 = su + Ra0*128 + ((((ks<<1)|kx) ^ (Ra0 & 7)) << 4);
            uint32_t ad1 = su + Ra1*128 + ((((ks<<1)|kx) ^ (Ra1 & 7)) << 4);
            LDSM4(a0[0],a0[1],a0[2],a0[3], ad0);
            LDSM4(a1[0],a1[1],a1[2],a1[3], ad1);
            #pragma unroll
            for (int ng = 0; ng < 4; ng++) {
                int na = nq*64 + ng*16 + ((bg >> 1) << 3) + bn;
                int seg = (ks << 1) | (bg & 1);
                uint32_t bd = bbase + na*128 + ((seg ^ (na & 7)) << 4);
                uint32_t r0, r1, r2, r3;
                LDSM4(r0, r1, r2, r3, bd);
                mma16816(acc[0][2*ng],   a0, r0, r1);
                mma16816(acc[1][2*ng],   a1, r0, r1);
                mma16816(acc[0][2*ng+1], a0, r2, r3);
                mma16816(acc[1][2*ng+1], a1, r2, r3);
            }
        }
    };

    for (int kc = 0; kc < 61; kc++) {
        // build A chunk (fp16), swizzled
        for (int e = tid; e < 4096; e += 256) {
            int pp = e >> 6, kk = e & 63;
            int k = kc*64 + kk;
            unsigned short hv16;
            if (k < 64) {
                hv16 = g_xh[(pos0+pp)*64 + k];
            } else if (k < 1344) {
                int u = k - 64; int t = u >> 6, c = u & 63;
                int gp = (b << 11) + s_id[pp*KNN + t];
                hv16 = g_xh[gp*64 + c];
            } else {
                int u = k - 1344;
                int ch = u & 255;
                float hv = g_h[(size_t)(pos0+pp)*2560 + u];
                float x = fmaf(s_a1[ch], hv, s_c1[ch]);
                float v = x > 0.f ? x : 0.01f*x;
                hv16 = fhb(v);
            }
            int off = pp*128 + (((kk >> 3) ^ (pp & 7)) << 4) + (kk & 7)*2;
            *(unsigned short*)(sm + off) = hv16;
        }
        uint32_t curbuf = (kc & 1) ? C2_B1 : C2_B0;
        if (kc + 1 < 61) {
            loadB(kc + 1, ((kc + 1) & 1) ? C2_B1 : C2_B0); CP_COMMIT();
            CP_WAIT1();
        } else {
            CP_WAIT0();
        }
        __syncthreads();
        combo(su + curbuf);
        __syncthreads();
    }

    #pragma unroll
    for (int mt = 0; mt < 2; mt++) {
        int Ra = mh*32 + mt*16 + (lane >> 2);
        int Rb = Ra + 8;
        #pragma unroll
        for (int nt = 0; nt < 8; nt++) {
            int co = nq*64 + nt*8 + (lane & 3)*2;
            float b0 = s_bi[co], b1v = s_bi[co+1];
            float2 v0; v0.x = acc[mt][nt][0] + b0; v0.y = acc[mt][nt][1] + b1v;
            *(float2*)&g_out2[(size_t)(pos0+Ra)*256 + co] = v0;
            float2 v1; v1.x = acc[mt][nt][2] + b0; v1.y = acc[mt][nt][3] + b1v;
            *(float2*)&g_out2[(size_t)(pos0+Rb)*256 + co] = v1;
        }
    }
}

// ---------------- BN2 + relu + final reshape ---------------------------------
__global__ __launch_bounds__(256) void k_final(float* __restrict__ out) {
    __shared__ float s_t[32][257];
    __shared__ float sa[CO2], sc[CO2];
    int bx = blockIdx.x;
    int b = bx >> 6, n0 = (bx & 63)*32;
    int tid = threadIdx.x;
    sa[tid] = g_a2[tid]; sc[tid] = g_c2[tid];
    for (int e = tid; e < 32*256; e += 256) {
        int nn = e >> 8, co = e & 255;
        s_t[nn][co] = g_out2[(size_t)((b << 11) + n0 + nn)*256 + co];
    }
    __syncthreads();
    for (int e = tid; e < 32*256; e += 256) {
        int co = e >> 5, nn = e & 31;
        float v = fmaf(sa[co], s_t[nn][co], sc[co]);
        out[(size_t)b*(128*4096) + (co >> 1)*4096 + ((co & 1) << 11) + n0 + nn] = fmaxf(v, 0.f);
    }
}

// ---------------- launch -----------------------------------------------------
extern "C" void kernel_launch(void* const* d_in, const int* in_sizes, int n_in,
                              void* d_out, int out_size) {
    const float* x   = (const float*)d_in[0];
    const float* w1  = (const float*)d_in[1];
    const float* b1  = (const float*)d_in[2];
    const float* g1  = (const float*)d_in[3];
    const float* be1 = (const float*)d_in[4];
    const float* w2  = (const float*)d_in[5];
    const float* b2  = (const float*)d_in[6];
    const float* g2  = (const float*)d_in[7];
    const float* be2 = (const float*)d_in[8];
    float* out = (float*)d_out;

    cudaFuncSetAttribute(k_conv1m, cudaFuncAttributeMaxDynamicSharedMemorySize, C1_SZ);
    cudaFuncSetAttribute(k_conv2m, cudaFuncAttributeMaxDynamicSharedMemorySize, C2_SZ);

    k_zero<<<1, 256>>>();
    k_xt<<<NPOS, 64>>>(x);
    k_w1m<<<12*16384/256, 256>>>(w1);
    k_w2m<<<61*16384/256, 256>>>(w2);
    k_dist<<<dim3(NPTS/64, NPTS/64, BB), 256>>>();
    k_knn<<<NPOS, 256>>>();
    k_conv1m<<<NPOS/16, 640, C1_SZ>>>(b1);
    k_stats1<<<128, 256>>>();
    k_bnfin<<<1, 256>>>(g1, be1, 0);
    k_conv2m<<<NPOS/64, 256, C2_SZ>>>(b2);
    k_stats2<<<128, 256>>>();
    k_bnfin<<<1, 256>>>(g2, be2, 1);
    k_final<<<BB*64, 256>>>(out);
}